// round 3
// baseline (speedup 1.0000x reference)
#include <cuda_runtime.h>
#include <math.h>

// Problem constants
#define BB   2
#define TT   1024
#define CC   2048
#define HH   16
#define DD   128
#define PP   1024
#define TOTL 2048          // PP + TT
#define BHN  32            // BB*HH

// Scratch (device globals; allocation-free at runtime)
__device__ float g_q  [(size_t)BHN * TT * DD];    // [b,h,t,d]   16MB
__device__ float g_att[(size_t)BHN * TT * TOTL];  // [bh,t,j]   256MB
__device__ float g_ao [(size_t)BB * TT * CC];     // [b,t,c]     16MB

// ---------------------------------------------------------------------------
// 64x64x16 fp32 tile GEMM core, double-buffered via register staging.
// Both A and B are loaded in "row = M/N index, col = K index" order (NT).
// ---------------------------------------------------------------------------

// ---------------------------------------------------------------------------
// Fused QKV projection: y = x @ W^T  (NT GEMM, M=N=K=2048), z selects W.
// q -> g_q [b,h,t,d]; k_new/v_new -> kv cache rows [b,h,1024+t,d]
// ---------------------------------------------------------------------------
__global__ void __launch_bounds__(128) qkv_kernel(
    const float* __restrict__ x,  const float* __restrict__ Wq,
    const float* __restrict__ Wk, const float* __restrict__ Wv,
    float* __restrict__ outk, float* __restrict__ outv)
{
    __shared__ float As[16][64];
    __shared__ float Bs[16][64];
    const int z = blockIdx.z;
    const float* __restrict__ W = (z == 0) ? Wq : (z == 1 ? Wk : Wv);
    const int m0 = blockIdx.y * 64, n0 = blockIdx.x * 64;
    const int tid = threadIdx.x;
    const int trow = (tid >> 3) * 4, tcol = (tid & 7) * 8;

    // load indices: each thread loads 2 float4 of A and 2 of B per tile
    const int r0 = tid >> 2,        c40 = (tid & 3) << 2;
    const int r1 = (tid + 128) >> 2, c41 = ((tid + 128) & 3) << 2;

    float acc[4][8];
#pragma unroll
    for (int i = 0; i < 4; i++)
#pragma unroll
        for (int j = 0; j < 8; j++) acc[i][j] = 0.f;

    // prefetch tile 0
    float4 a0 = *(const float4*)&x[(size_t)(m0 + r0) * 2048 + c40];
    float4 a1 = *(const float4*)&x[(size_t)(m0 + r1) * 2048 + c41];
    float4 b0 = *(const float4*)&W[(size_t)(n0 + r0) * 2048 + c40];
    float4 b1 = *(const float4*)&W[(size_t)(n0 + r1) * 2048 + c41];

    for (int k0 = 0; k0 < 2048; k0 += 16) {
        As[c40 + 0][r0] = a0.x; As[c40 + 1][r0] = a0.y;
        As[c40 + 2][r0] = a0.z; As[c40 + 3][r0] = a0.w;
        As[c41 + 0][r1] = a1.x; As[c41 + 1][r1] = a1.y;
        As[c41 + 2][r1] = a1.z; As[c41 + 3][r1] = a1.w;
        Bs[c40 + 0][r0] = b0.x; Bs[c40 + 1][r0] = b0.y;
        Bs[c40 + 2][r0] = b0.z; Bs[c40 + 3][r0] = b0.w;
        Bs[c41 + 0][r1] = b1.x; Bs[c41 + 1][r1] = b1.y;
        Bs[c41 + 2][r1] = b1.z; Bs[c41 + 3][r1] = b1.w;
        __syncthreads();
        if (k0 + 16 < 2048) {
            int kn = k0 + 16;
            a0 = *(const float4*)&x[(size_t)(m0 + r0) * 2048 + kn + c40];
            a1 = *(const float4*)&x[(size_t)(m0 + r1) * 2048 + kn + c41];
            b0 = *(const float4*)&W[(size_t)(n0 + r0) * 2048 + kn + c40];
            b1 = *(const float4*)&W[(size_t)(n0 + r1) * 2048 + kn + c41];
        }
#pragma unroll
        for (int kk = 0; kk < 16; kk++) {
            float4 av4 = *(const float4*)&As[kk][trow];
            float4 bv0 = *(const float4*)&Bs[kk][tcol];
            float4 bv1 = *(const float4*)&Bs[kk][tcol + 4];
            float av[4] = {av4.x, av4.y, av4.z, av4.w};
            float bv[8] = {bv0.x, bv0.y, bv0.z, bv0.w, bv1.x, bv1.y, bv1.z, bv1.w};
#pragma unroll
            for (int i = 0; i < 4; i++)
#pragma unroll
                for (int j = 0; j < 8; j++)
                    acc[i][j] = fmaf(av[i], bv[j], acc[i][j]);
        }
        __syncthreads();
    }

#pragma unroll
    for (int i = 0; i < 4; i++) {
        int m = m0 + trow + i;
        int b = m >> 10, t = m & 1023;
#pragma unroll
        for (int j = 0; j < 8; j++) {
            int n = n0 + tcol + j;
            int h = n >> 7, d = n & 127;
            float val = acc[i][j];
            if (z == 0) {
                g_q[(((size_t)(b * 16 + h)) * 1024 + t) * 128 + d] = val;
            } else {
                float* dst = (z == 1) ? outk : outv;
                dst[(((size_t)(b * 16 + h)) * 2048 + 1024 + t) * 128 + d] = val;
            }
        }
    }
}

// ---------------------------------------------------------------------------
// Copy past_k / past_v into kv cache rows [0,1024)
// ---------------------------------------------------------------------------
__global__ void copy_past_kernel(const float4* __restrict__ pk,
                                 const float4* __restrict__ pv,
                                 float4* __restrict__ outk,
                                 float4* __restrict__ outv)
{
    const int n4 = BB * HH * PP * DD / 4;  // 1048576 per tensor
    int idx = blockIdx.x * blockDim.x + threadIdx.x;
    if (idx >= 2 * n4) return;
    const float4* src;
    float4* dst;
    int i;
    if (idx < n4) { src = pk; dst = outk; i = idx; }
    else          { src = pv; dst = outv; i = idx - n4; }
    int bh  = i >> 15;        // / (PP*DD/4)
    int rem = i & 32767;
    dst[(size_t)bh * (TOTL * DD / 4) + rem] = src[i];
}

// ---------------------------------------------------------------------------
// Scores: S[bh, t, j] = scale * q[bh,t,:] . k[bh,j,:]   (NT, K=128)
// Fully masked 64x64 tiles skipped; partially-masked values computed but
// zeroed by the masked softmax.
// ---------------------------------------------------------------------------
__global__ void __launch_bounds__(128) scores_kernel(const float* __restrict__ kf)
{
    const int bh = blockIdx.z;
    const int n0 = blockIdx.x * 64;   // j
    const int m0 = blockIdx.y * 64;   // t
    if (n0 > 1024 + m0 + 63) return;  // entire tile masked

    const float* __restrict__ A  = g_q  + (size_t)bh * TT * DD;
    const float* __restrict__ Bm = kf   + (size_t)bh * TOTL * DD;
    float*       __restrict__ Cm = g_att + (size_t)bh * TT * TOTL;

    __shared__ float As[16][64];
    __shared__ float Bs[16][64];
    const int tid = threadIdx.x;
    const int trow = (tid >> 3) * 4, tcol = (tid & 7) * 8;
    const int r0 = tid >> 2,         c40 = (tid & 3) << 2;
    const int r1 = (tid + 128) >> 2, c41 = ((tid + 128) & 3) << 2;

    float acc[4][8];
#pragma unroll
    for (int i = 0; i < 4; i++)
#pragma unroll
        for (int j = 0; j < 8; j++) acc[i][j] = 0.f;

    float4 a0 = *(const float4*)&A[(size_t)(m0 + r0) * 128 + c40];
    float4 a1 = *(const float4*)&A[(size_t)(m0 + r1) * 128 + c41];
    float4 b0 = *(const float4*)&Bm[(size_t)(n0 + r0) * 128 + c40];
    float4 b1 = *(const float4*)&Bm[(size_t)(n0 + r1) * 128 + c41];

    for (int k0 = 0; k0 < 128; k0 += 16) {
        As[c40 + 0][r0] = a0.x; As[c40 + 1][r0] = a0.y;
        As[c40 + 2][r0] = a0.z; As[c40 + 3][r0] = a0.w;
        As[c41 + 0][r1] = a1.x; As[c41 + 1][r1] = a1.y;
        As[c41 + 2][r1] = a1.z; As[c41 + 3][r1] = a1.w;
        Bs[c40 + 0][r0] = b0.x; Bs[c40 + 1][r0] = b0.y;
        Bs[c40 + 2][r0] = b0.z; Bs[c40 + 3][r0] = b0.w;
        Bs[c41 + 0][r1] = b1.x; Bs[c41 + 1][r1] = b1.y;
        Bs[c41 + 2][r1] = b1.z; Bs[c41 + 3][r1] = b1.w;
        __syncthreads();
        if (k0 + 16 < 128) {
            int kn = k0 + 16;
            a0 = *(const float4*)&A[(size_t)(m0 + r0) * 128 + kn + c40];
            a1 = *(const float4*)&A[(size_t)(m0 + r1) * 128 + kn + c41];
            b0 = *(const float4*)&Bm[(size_t)(n0 + r0) * 128 + kn + c40];
            b1 = *(const float4*)&Bm[(size_t)(n0 + r1) * 128 + kn + c41];
        }
#pragma unroll
        for (int kk = 0; kk < 16; kk++) {
            float4 av4 = *(const float4*)&As[kk][trow];
            float4 bv0 = *(const float4*)&Bs[kk][tcol];
            float4 bv1 = *(const float4*)&Bs[kk][tcol + 4];
            float av[4] = {av4.x, av4.y, av4.z, av4.w};
            float bv[8] = {bv0.x, bv0.y, bv0.z, bv0.w, bv1.x, bv1.y, bv1.z, bv1.w};
#pragma unroll
            for (int i = 0; i < 4; i++)
#pragma unroll
                for (int j = 0; j < 8; j++)
                    acc[i][j] = fmaf(av[i], bv[j], acc[i][j]);
        }
        __syncthreads();
    }

    const float scale = 0.08838834764831845f;  // 1/sqrt(128)
#pragma unroll
    for (int i = 0; i < 4; i++)
#pragma unroll
        for (int j = 0; j < 8; j++)
            Cm[(size_t)(m0 + trow + i) * 2048 + n0 + tcol + j] = acc[i][j] * scale;
}

// ---------------------------------------------------------------------------
// Masked softmax per row. Row t attends j <= 1024 + t, so j in [0,1024) is
// always valid; masked tail entries are written as 0 (so PV GEMM is unmasked).
// ---------------------------------------------------------------------------
__global__ void __launch_bounds__(256) softmax_kernel()
{
    __shared__ float red[256];
    const int row = blockIdx.x;          // 0..32767  = bh*1024 + t
    const int t = row & 1023;
    float4* p4 = (float4*)(g_att + (size_t)row * 2048);
    const int tx = threadIdx.x;

    float4 v0 = p4[tx];          // j in [0,1024)
    float4 v1 = p4[tx + 256];    // j = 1024 + tx*4 + l, valid iff tx*4+l <= t
    const int b1 = tx * 4;
    float vv[4] = {v1.x, v1.y, v1.z, v1.w};

    float m = fmaxf(fmaxf(v0.x, v0.y), fmaxf(v0.z, v0.w));
#pragma unroll
    for (int l = 0; l < 4; l++)
        if (b1 + l <= t) m = fmaxf(m, vv[l]);

    red[tx] = m; __syncthreads();
    for (int s = 128; s > 0; s >>= 1) {
        if (tx < s) red[tx] = fmaxf(red[tx], red[tx + s]);
        __syncthreads();
    }
    m = red[0];
    __syncthreads();

    float e0[4];
    e0[0] = __expf(v0.x - m); e0[1] = __expf(v0.y - m);
    e0[2] = __expf(v0.z - m); e0[3] = __expf(v0.w - m);
    float e1[4];
#pragma unroll
    for (int l = 0; l < 4; l++)
        e1[l] = (b1 + l <= t) ? __expf(vv[l] - m) : 0.f;

    float s = e0[0] + e0[1] + e0[2] + e0[3] + e1[0] + e1[1] + e1[2] + e1[3];
    red[tx] = s; __syncthreads();
    for (int st = 128; st > 0; st >>= 1) {
        if (tx < st) red[tx] += red[tx + st];
        __syncthreads();
    }
    float inv = 1.f / red[0];

    float4 o0 = make_float4(e0[0] * inv, e0[1] * inv, e0[2] * inv, e0[3] * inv);
    float4 o1 = make_float4(e1[0] * inv, e1[1] * inv, e1[2] * inv, e1[3] * inv);
    p4[tx] = o0;
    p4[tx + 256] = o1;
}

// ---------------------------------------------------------------------------
// PV: O[bh, t, d] = sum_j att[bh,t,j] * v[bh,j,d]   (NN, K=2048, N=128)
// Written directly into [B,T,C] layout (g_ao).
// ---------------------------------------------------------------------------
__global__ void __launch_bounds__(128) pv_kernel(const float* __restrict__ vf)
{
    const int bh = blockIdx.z;
    const int b = bh >> 4, h = bh & 15;
    const int n0 = blockIdx.x * 64;   // d
    const int m0 = blockIdx.y * 64;   // t

    const float* __restrict__ A  = g_att + (size_t)bh * TT * TOTL;
    const float* __restrict__ Bm = vf    + (size_t)bh * TOTL * DD;

    __shared__ float As[16][64];
    __shared__ float Bs[16][64];
    const int tid = threadIdx.x;
    const int trow = (tid >> 3) * 4, tcol = (tid & 7) * 8;
    const int r0 = tid >> 2,         c40 = (tid & 3) << 2;
    const int r1 = (tid + 128) >> 2, c41 = ((tid + 128) & 3) << 2;
    const int rb0 = tid >> 4,          cb0 = (tid & 15) << 2;
    const int rb1 = (tid + 128) >> 4,  cb1 = ((tid + 128) & 15) << 2;

    float acc[4][8];
#pragma unroll
    for (int i = 0; i < 4; i++)
#pragma unroll
        for (int j = 0; j < 8; j++) acc[i][j] = 0.f;

    float4 a0 = *(const float4*)&A[(size_t)(m0 + r0) * 2048 + c40];
    float4 a1 = *(const float4*)&A[(size_t)(m0 + r1) * 2048 + c41];
    float4 b0 = *(const float4*)&Bm[(size_t)rb0 * 128 + n0 + cb0];
    float4 b1 = *(const float4*)&Bm[(size_t)rb1 * 128 + n0 + cb1];

    for (int k0 = 0; k0 < 2048; k0 += 16) {
        As[c40 + 0][r0] = a0.x; As[c40 + 1][r0] = a0.y;
        As[c40 + 2][r0] = a0.z; As[c40 + 3][r0] = a0.w;
        As[c41 + 0][r1] = a1.x; As[c41 + 1][r1] = a1.y;
        As[c41 + 2][r1] = a1.z; As[c41 + 3][r1] = a1.w;
        Bs[rb0][cb0 + 0] = b0.x; Bs[rb0][cb0 + 1] = b0.y;
        Bs[rb0][cb0 + 2] = b0.z; Bs[rb0][cb0 + 3] = b0.w;
        Bs[rb1][cb1 + 0] = b1.x; Bs[rb1][cb1 + 1] = b1.y;
        Bs[rb1][cb1 + 2] = b1.z; Bs[rb1][cb1 + 3] = b1.w;
        __syncthreads();
        if (k0 + 16 < 2048) {
            int kn = k0 + 16;
            a0 = *(const float4*)&A[(size_t)(m0 + r0) * 2048 + kn + c40];
            a1 = *(const float4*)&A[(size_t)(m0 + r1) * 2048 + kn + c41];
            b0 = *(const float4*)&Bm[(size_t)(kn + rb0) * 128 + n0 + cb0];
            b1 = *(const float4*)&Bm[(size_t)(kn + rb1) * 128 + n0 + cb1];
        }
#pragma unroll
        for (int kk = 0; kk < 16; kk++) {
            float4 av4 = *(const float4*)&As[kk][trow];
            float4 bv0 = *(const float4*)&Bs[kk][tcol];
            float4 bv1 = *(const float4*)&Bs[kk][tcol + 4];
            float av[4] = {av4.x, av4.y, av4.z, av4.w};
            float bv[8] = {bv0.x, bv0.y, bv0.z, bv0.w, bv1.x, bv1.y, bv1.z, bv1.w};
#pragma unroll
            for (int i = 0; i < 4; i++)
#pragma unroll
                for (int j = 0; j < 8; j++)
                    acc[i][j] = fmaf(av[i], bv[j], acc[i][j]);
        }
        __syncthreads();
    }

#pragma unroll
    for (int i = 0; i < 4; i++) {
        int t = m0 + trow + i;
#pragma unroll
        for (int j = 0; j < 8; j++) {
            int d = n0 + tcol + j;
            g_ao[((size_t)(b * 1024 + t)) * 2048 + h * 128 + d] = acc[i][j];
        }
    }
}

// ---------------------------------------------------------------------------
// Output projection: out = g_ao @ Wp^T + bp   (NT, M=N=K=2048)
// ---------------------------------------------------------------------------
__global__ void __launch_bounds__(128) proj_kernel(const float* __restrict__ Wp,
                                                   const float* __restrict__ bp,
                                                   float* __restrict__ out)
{
    __shared__ float As[16][64];
    __shared__ float Bs[16][64];
    const int m0 = blockIdx.y * 64, n0 = blockIdx.x * 64;
    const int tid = threadIdx.x;
    const int trow = (tid >> 3) * 4, tcol = (tid & 7) * 8;
    const int r0 = tid >> 2,         c40 = (tid & 3) << 2;
    const int r1 = (tid + 128) >> 2, c41 = ((tid + 128) & 3) << 2;

    float acc[4][8];
#pragma unroll
    for (int i = 0; i < 4; i++)
#pragma unroll
        for (int j = 0; j < 8; j++) acc[i][j] = 0.f;

    float4 a0 = *(const float4*)&g_ao[(size_t)(m0 + r0) * 2048 + c40];
    float4 a1 = *(const float4*)&g_ao[(size_t)(m0 + r1) * 2048 + c41];
    float4 b0 = *(const float4*)&Wp[(size_t)(n0 + r0) * 2048 + c40];
    float4 b1 = *(const float4*)&Wp[(size_t)(n0 + r1) * 2048 + c41];

    for (int k0 = 0; k0 < 2048; k0 += 16) {
        As[c40 + 0][r0] = a0.x; As[c40 + 1][r0] = a0.y;
        As[c40 + 2][r0] = a0.z; As[c40 + 3][r0] = a0.w;
        As[c41 + 0][r1] = a1.x; As[c41 + 1][r1] = a1.y;
        As[c41 + 2][r1] = a1.z; As[c41 + 3][r1] = a1.w;
        Bs[c40 + 0][r0] = b0.x; Bs[c40 + 1][r0] = b0.y;
        Bs[c40 + 2][r0] = b0.z; Bs[c40 + 3][r0] = b0.w;
        Bs[c41 + 0][r1] = b1.x; Bs[c41 + 1][r1] = b1.y;
        Bs[c41 + 2][r1] = b1.z; Bs[c41 + 3][r1] = b1.w;
        __syncthreads();
        if (k0 + 16 < 2048) {
            int kn = k0 + 16;
            a0 = *(const float4*)&g_ao[(size_t)(m0 + r0) * 2048 + kn + c40];
            a1 = *(const float4*)&g_ao[(size_t)(m0 + r1) * 2048 + kn + c41];
            b0 = *(const float4*)&Wp[(size_t)(n0 + r0) * 2048 + kn + c40];
            b1 = *(const float4*)&Wp[(size_t)(n0 + r1) * 2048 + kn + c41];
        }
#pragma unroll
        for (int kk = 0; kk < 16; kk++) {
            float4 av4 = *(const float4*)&As[kk][trow];
            float4 bv0 = *(const float4*)&Bs[kk][tcol];
            float4 bv1 = *(const float4*)&Bs[kk][tcol + 4];
            float av[4] = {av4.x, av4.y, av4.z, av4.w};
            float bv[8] = {bv0.x, bv0.y, bv0.z, bv0.w, bv1.x, bv1.y, bv1.z, bv1.w};
#pragma unroll
            for (int i = 0; i < 4; i++)
#pragma unroll
                for (int j = 0; j < 8; j++)
                    acc[i][j] = fmaf(av[i], bv[j], acc[i][j]);
        }
        __syncthreads();
    }

#pragma unroll
    for (int i = 0; i < 4; i++) {
        int m = m0 + trow + i;
#pragma unroll
        for (int j = 0; j < 8; j++) {
            int n = n0 + tcol + j;
            out[(size_t)m * 2048 + n] = acc[i][j] + __ldg(&bp[n]);
        }
    }
}

// ---------------------------------------------------------------------------
extern "C" void kernel_launch(void* const* d_in, const int* in_sizes, int n_in,
                              void* d_out, int out_size)
{
    (void)in_sizes; (void)n_in; (void)out_size;
    const float* x      = (const float*)d_in[0];
    const float* past_k = (const float*)d_in[1];
    const float* past_v = (const float*)d_in[2];
    const float* Wk     = (const float*)d_in[3];
    const float* Wq     = (const float*)d_in[4];
    const float* Wv     = (const float*)d_in[5];
    const float* Wp     = (const float*)d_in[6];
    const float* bp     = (const float*)d_in[7];

    float* out  = (float*)d_out;                 // [B,T,C]       4,194,304
    float* outk = out + (size_t)BB * TT * CC;    // [B,H,2048,D]  8,388,608
    float* outv = outk + (size_t)BHN * TOTL * DD;

    // 1. past KV -> cache
    copy_past_kernel<<<8192, 256>>>((const float4*)past_k, (const float4*)past_v,
                                    (float4*)outk, (float4*)outv);
    // 2. fused QKV projection
    qkv_kernel<<<dim3(32, 32, 3), 128>>>(x, Wq, Wk, Wv, outk, outv);
    // 3. attention scores (masked tiles skipped)
    scores_kernel<<<dim3(32, 16, 32), 128>>>(outk);
    // 4. masked softmax
    softmax_kernel<<<32768, 256>>>();
    // 5. P @ V
    pv_kernel<<<dim3(2, 16, 32), 128>>>(outv);
    // 6. output projection + bias
    proj_kernel<<<dim3(32, 32), 128>>>(Wp, bp, out);
}

// round 5
// speedup vs baseline: 3.5587x; 3.5587x over previous
#include <cuda_runtime.h>
#include <cuda_bf16.h>
#include <math.h>
#include <stdint.h>

// Problem constants
#define BB   2
#define TT   1024
#define CC   2048
#define HH   16
#define DD   128
#define PP   1024
#define TOTL 2048
#define BHN  32

// ---------------------------------------------------------------------------
// Device scratch (allocation-free)
// ---------------------------------------------------------------------------
__device__ float         g_att[(size_t)BHN * TT * TOTL];      // fp32 scores
__device__ __nv_bfloat16 g_xh [(size_t)CC * CC], g_xl [(size_t)CC * CC];
__device__ __nv_bfloat16 g_wqh[(size_t)CC * CC], g_wql[(size_t)CC * CC];
__device__ __nv_bfloat16 g_wkh[(size_t)CC * CC], g_wkl[(size_t)CC * CC];
__device__ __nv_bfloat16 g_wvh[(size_t)CC * CC], g_wvl[(size_t)CC * CC];
__device__ __nv_bfloat16 g_wph[(size_t)CC * CC], g_wpl[(size_t)CC * CC];
__device__ __nv_bfloat16 g_qh [(size_t)BHN * TT * DD],   g_ql [(size_t)BHN * TT * DD];
__device__ __nv_bfloat16 g_kh [(size_t)BHN * TOTL * DD], g_kl [(size_t)BHN * TOTL * DD];
__device__ __nv_bfloat16 g_vth[(size_t)BHN * DD * TOTL], g_vtl[(size_t)BHN * DD * TOTL];
__device__ __nv_bfloat16 g_ah [(size_t)BHN * TT * TOTL], g_al [(size_t)BHN * TT * TOTL];
__device__ __nv_bfloat16 g_aoh[(size_t)BB * TT * CC],    g_aol[(size_t)BB * TT * CC];

__device__ __forceinline__ uint32_t smem_u32(const void* p) {
    uint32_t a;
    asm("{ .reg .u64 t; cvta.to.shared.u64 t, %1; cvt.u32.u64 %0, t; }" : "=r"(a) : "l"(p));
    return a;
}
__device__ __forceinline__ void split2(float v, __nv_bfloat16& h, __nv_bfloat16& l) {
    h = __float2bfloat16(v);
    l = __float2bfloat16(v - __bfloat162float(h));
}

#define LDM4(r, addr)                                                        \
    asm volatile("ldmatrix.sync.aligned.m8n8.x4.shared.b16 {%0,%1,%2,%3}, [%4];" \
        : "=r"((r)[0]), "=r"((r)[1]), "=r"((r)[2]), "=r"((r)[3]) : "r"(addr))

#define MMA16816(c, a, b0v, b1v)                                             \
    asm volatile("mma.sync.aligned.m16n8k16.row.col.f32.bf16.bf16.f32 "      \
        "{%0,%1,%2,%3}, {%4,%5,%6,%7}, {%8,%9}, {%0,%1,%2,%3};"              \
        : "+f"((c)[0]), "+f"((c)[1]), "+f"((c)[2]), "+f"((c)[3])             \
        : "r"((a)[0]), "r"((a)[1]), "r"((a)[2]), "r"((a)[3]),                \
          "r"(b0v), "r"(b1v))

// SW64-style swizzle for 64B rows (32 bf16): conflict-free ldmatrix + stores
__device__ __forceinline__ uint32_t swz(uint32_t o) { return o ^ ((o >> 3) & 0x30); }

// ---------------------------------------------------------------------------
// Warp-MMA mainloop.
// CTA 256 thr = 8 warps (grid 4x2). CTA tile 128(m) x 128(n), K-chunk 32.
// A = Ah+Al [m,k] row-major; B = Bh+Bl [n,k] row-major (NT GEMM).
// 3-term: C = AhBh + AhBl + AlBh, fp32 accumulators.
// smem: 4 tiles of 128x32 bf16 (8KB each): Ah, Al, Bh, Bl.
// ---------------------------------------------------------------------------
struct Frag { float c[2][8][4]; };

__device__ __forceinline__ void mma_mainloop(
    char* smem,   // 32KB
    const __nv_bfloat16* __restrict__ Ah, const __nv_bfloat16* __restrict__ Al,
    const __nv_bfloat16* __restrict__ Bh, const __nv_bfloat16* __restrict__ Bl,
    size_t ldA, size_t ldB, int NC, Frag& F)
{
    const uint32_t sb = smem_u32(smem);
    const int tid  = threadIdx.x;
    const int lane = tid & 31;
    const int wid  = tid >> 5;
    const int wm   = wid & 3;      // 0..3 -> 32-row group
    const int wn   = wid >> 2;     // 0..1 -> 64-col group

#pragma unroll
    for (int i = 0; i < 2; i++)
#pragma unroll
        for (int j = 0; j < 8; j++)
#pragma unroll
            for (int k = 0; k < 4; k++) F.c[i][j][k] = 0.f;

    // global load mapping: 8 uint4 per thread per chunk; tile T = j>>1
    int lrow[8], lun[8];
#pragma unroll
    for (int j = 0; j < 8; j++) {
        int u = tid + 256 * (j & 1);
        lrow[j] = u >> 2; lun[j] = u & 3;
    }
    const __nv_bfloat16* srcs[4] = {Ah, Al, Bh, Bl};
    const size_t lds[4] = {ldA, ldA, ldB, ldB};

    // fragment smem offsets (tile-relative, swizzled)
    uint32_t aoff[2][2], boff[4][2];
#pragma unroll
    for (int mt = 0; mt < 2; mt++)
#pragma unroll
        for (int kk = 0; kk < 2; kk++) {
            int row = wm * 32 + mt * 16 + (lane & 15);
            aoff[mt][kk] = swz(row * 64 + kk * 32 + ((lane >> 4) & 1) * 16);
        }
#pragma unroll
    for (int bt = 0; bt < 4; bt++)
#pragma unroll
        for (int kk = 0; kk < 2; kk++) {
            int row = wn * 64 + bt * 16 + (lane & 7) + ((lane >> 4) & 1) * 8;
            boff[bt][kk] = swz(row * 64 + kk * 32 + ((lane >> 3) & 1) * 16);
        }

    uint4 stg[8];
#pragma unroll
    for (int j = 0; j < 8; j++) {
        int T = j >> 1;
        stg[j] = *(const uint4*)(srcs[T] + (size_t)lrow[j] * lds[T] + lun[j] * 8);
    }

    for (int ch = 0; ch < NC; ch++) {
#pragma unroll
        for (int j = 0; j < 8; j++) {
            int T = j >> 1;
            *(uint4*)(smem + T * 8192 + swz(lrow[j] * 64 + lun[j] * 16)) = stg[j];
        }
        __syncthreads();
        if (ch + 1 < NC) {
            size_t k0 = (size_t)(ch + 1) * 32;
#pragma unroll
            for (int j = 0; j < 8; j++) {
                int T = j >> 1;
                stg[j] = *(const uint4*)(srcs[T] + (size_t)lrow[j] * lds[T] + k0 + lun[j] * 8);
            }
        }
#pragma unroll
        for (int kk = 0; kk < 2; kk++) {
            uint32_t ah[2][4], al[2][4], bh4[4][4], bl4[4][4];
#pragma unroll
            for (int mt = 0; mt < 2; mt++) LDM4(ah[mt], sb + 0 + aoff[mt][kk]);
#pragma unroll
            for (int bt = 0; bt < 4; bt++) LDM4(bh4[bt], sb + 16384 + boff[bt][kk]);
#pragma unroll
            for (int mt = 0; mt < 2; mt++)
#pragma unroll
                for (int bt = 0; bt < 4; bt++) {
                    MMA16816(F.c[mt][bt * 2 + 0], ah[mt], bh4[bt][0], bh4[bt][1]);
                    MMA16816(F.c[mt][bt * 2 + 1], ah[mt], bh4[bt][2], bh4[bt][3]);
                }
#pragma unroll
            for (int bt = 0; bt < 4; bt++) LDM4(bl4[bt], sb + 24576 + boff[bt][kk]);
#pragma unroll
            for (int mt = 0; mt < 2; mt++)
#pragma unroll
                for (int bt = 0; bt < 4; bt++) {
                    MMA16816(F.c[mt][bt * 2 + 0], ah[mt], bl4[bt][0], bl4[bt][1]);
                    MMA16816(F.c[mt][bt * 2 + 1], ah[mt], bl4[bt][2], bl4[bt][3]);
                }
#pragma unroll
            for (int mt = 0; mt < 2; mt++) LDM4(al[mt], sb + 8192 + aoff[mt][kk]);
#pragma unroll
            for (int mt = 0; mt < 2; mt++)
#pragma unroll
                for (int bt = 0; bt < 4; bt++) {
                    MMA16816(F.c[mt][bt * 2 + 0], al[mt], bh4[bt][0], bh4[bt][1]);
                    MMA16816(F.c[mt][bt * 2 + 1], al[mt], bh4[bt][2], bh4[bt][3]);
                }
        }
        __syncthreads();
    }
}

// Epilogue index helpers: element (mt, nt, ci) sits at
//   row = wm*32 + mt*16 + lane/4 + (ci>=2 ? 8 : 0)
//   col = wn*64 + nt*8 + (lane%4)*2 + (ci&1)      (pairs c0,c1 / c2,c3 contiguous)

// ---------------------------------------------------------------------------
// Conversion + aux kernels
// ---------------------------------------------------------------------------
__global__ void __launch_bounds__(256) split_kernel(
    const float4* __restrict__ src, __nv_bfloat162* __restrict__ dh,
    __nv_bfloat162* __restrict__ dl, int n4)
{
    int i = blockIdx.x * blockDim.x + threadIdx.x;
    if (i >= n4) return;
    float4 v = src[i];
    __nv_bfloat16 h0, h1, h2, h3, l0, l1, l2, l3;
    split2(v.x, h0, l0); split2(v.y, h1, l1);
    split2(v.z, h2, l2); split2(v.w, h3, l3);
    __nv_bfloat162 H0; H0.x = h0; H0.y = h1;
    __nv_bfloat162 H1; H1.x = h2; H1.y = h3;
    __nv_bfloat162 L0; L0.x = l0; L0.y = l1;
    __nv_bfloat162 L1; L1.x = l2; L1.y = l3;
    dh[2 * i] = H0; dh[2 * i + 1] = H1;
    dl[2 * i] = L0; dl[2 * i + 1] = L1;
}

// v[bh][j][d] fp32 -> vt hi/lo [bh][d][j] bf16
__global__ void __launch_bounds__(256) vtrans_kernel(const float* __restrict__ v)
{
    __shared__ float tile[32][33];
    const int bh = blockIdx.z;
    const int j0 = blockIdx.x * 32, d0 = blockIdx.y * 32;
    const int tx = threadIdx.x & 31, ty = threadIdx.x >> 5;   // 32x8
    const float* src = v + (size_t)bh * TOTL * DD;
#pragma unroll
    for (int i = 0; i < 4; i++)
        tile[ty + i * 8][tx] = src[(size_t)(j0 + ty + i * 8) * DD + d0 + tx];
    __syncthreads();
    __nv_bfloat16* dh = g_vth + (size_t)bh * DD * TOTL;
    __nv_bfloat16* dl = g_vtl + (size_t)bh * DD * TOTL;
#pragma unroll
    for (int i = 0; i < 4; i++) {
        int d = d0 + ty + i * 8, j = j0 + tx;
        float val = tile[tx][ty + i * 8];
        __nv_bfloat16 h, l; split2(val, h, l);
        dh[(size_t)d * TOTL + j] = h;
        dl[(size_t)d * TOTL + j] = l;
    }
}

__global__ void copy_past_kernel(const float4* __restrict__ pk,
                                 const float4* __restrict__ pv,
                                 float4* __restrict__ outk,
                                 float4* __restrict__ outv)
{
    const int n4 = BB * HH * PP * DD / 4;
    int idx = blockIdx.x * blockDim.x + threadIdx.x;
    if (idx >= 2 * n4) return;
    const float4* src; float4* dst; int i;
    if (idx < n4) { src = pk; dst = outk; i = idx; }
    else          { src = pv; dst = outv; i = idx - n4; }
    int bh = i >> 15, rem = i & 32767;
    dst[(size_t)bh * (TOTL * DD / 4) + rem] = src[i];
}

// ---------------------------------------------------------------------------
// QKV projection: y = x @ W^T, z selects {Wq, Wk, Wv}
// ---------------------------------------------------------------------------
__global__ void __launch_bounds__(256) qkv_mma(float* __restrict__ outk,
                                               float* __restrict__ outv)
{
    __shared__ __align__(1024) char smem[32768];
    const int z = blockIdx.z;
    const int m0 = blockIdx.y * 128, n0 = blockIdx.x * 128;
    const __nv_bfloat16* Bh = (z == 0) ? g_wqh : (z == 1) ? g_wkh : g_wvh;
    const __nv_bfloat16* Bl = (z == 0) ? g_wql : (z == 1) ? g_wkl : g_wvl;
    Frag F;
    mma_mainloop(smem,
        g_xh + (size_t)m0 * CC, g_xl + (size_t)m0 * CC,
        Bh + (size_t)n0 * CC,   Bl + (size_t)n0 * CC, CC, CC, 64, F);

    const int lane = threadIdx.x & 31, wid = threadIdx.x >> 5;
    const int wm = wid & 3, wn = wid >> 2;
#pragma unroll
    for (int mt = 0; mt < 2; mt++)
#pragma unroll
        for (int half = 0; half < 2; half++) {
            int m = m0 + wm * 32 + mt * 16 + lane / 4 + half * 8;
            int b = m >> 10, t = m & 1023;
#pragma unroll
            for (int nt = 0; nt < 8; nt++) {
                int n = n0 + wn * 64 + nt * 8 + (lane & 3) * 2;
                int h = n >> 7, d = n & 127;
                float v0 = F.c[mt][nt][half * 2], v1 = F.c[mt][nt][half * 2 + 1];
                if (z == 0) {
                    size_t base = (((size_t)(b * 16 + h)) * 1024 + t) * 128 + d;
                    __nv_bfloat16 h0, h1, l0, l1;
                    split2(v0, h0, l0); split2(v1, h1, l1);
                    __nv_bfloat162 H; H.x = h0; H.y = h1;
                    __nv_bfloat162 L; L.x = l0; L.y = l1;
                    *(__nv_bfloat162*)(g_qh + base) = H;
                    *(__nv_bfloat162*)(g_ql + base) = L;
                } else {
                    float* dst = (z == 1) ? outk : outv;
                    size_t base = (((size_t)(b * 16 + h)) * 2048 + 1024 + t) * 128 + d;
                    *(float2*)(dst + base) = make_float2(v0, v1);
                }
            }
        }
}

// ---------------------------------------------------------------------------
// Scores: S[bh,t,j] = scale * q . k   (fully-masked tiles skipped)
// ---------------------------------------------------------------------------
__global__ void __launch_bounds__(256) scores_mma()
{
    __shared__ __align__(1024) char smem[32768];
    const int bh = blockIdx.z;
    const int m0 = blockIdx.y * 128;   // t
    const int n0 = blockIdx.x * 128;   // j
    if (n0 > 1151 + m0) return;

    Frag F;
    mma_mainloop(smem,
        g_qh + ((size_t)bh * TT + m0) * DD,   g_ql + ((size_t)bh * TT + m0) * DD,
        g_kh + ((size_t)bh * TOTL + n0) * DD, g_kl + ((size_t)bh * TOTL + n0) * DD,
        DD, DD, 4, F);

    const int lane = threadIdx.x & 31, wid = threadIdx.x >> 5;
    const int wm = wid & 3, wn = wid >> 2;
    const float scale = 0.08838834764831845f;
#pragma unroll
    for (int mt = 0; mt < 2; mt++)
#pragma unroll
        for (int half = 0; half < 2; half++) {
            int t = m0 + wm * 32 + mt * 16 + lane / 4 + half * 8;
            float* dst = g_att + ((size_t)bh * TT + t) * TOTL;
#pragma unroll
            for (int nt = 0; nt < 8; nt++) {
                int n = n0 + wn * 64 + nt * 8 + (lane & 3) * 2;
                *(float2*)(dst + n) = make_float2(F.c[mt][nt][half * 2] * scale,
                                                  F.c[mt][nt][half * 2 + 1] * scale);
            }
        }
}

// ---------------------------------------------------------------------------
// Masked softmax: fp32 g_att -> split bf16 g_ah/g_al (masked = 0)
// ---------------------------------------------------------------------------
__global__ void __launch_bounds__(256) softmax_kernel()
{
    __shared__ float red[256];
    const int row = blockIdx.x;          // bh*1024 + t
    const int t = row & 1023;
    const float4* p4 = (const float4*)(g_att + (size_t)row * 2048);
    const int tx = threadIdx.x;

    float4 v0 = p4[tx];
    float4 v1 = p4[tx + 256];
    const int b1 = tx * 4;
    float vv[4] = {v1.x, v1.y, v1.z, v1.w};

    float m = fmaxf(fmaxf(v0.x, v0.y), fmaxf(v0.z, v0.w));
#pragma unroll
    for (int l = 0; l < 4; l++)
        if (b1 + l <= t) m = fmaxf(m, vv[l]);

    red[tx] = m; __syncthreads();
    for (int s = 128; s > 0; s >>= 1) {
        if (tx < s) red[tx] = fmaxf(red[tx], red[tx + s]);
        __syncthreads();
    }
    m = red[0];
    __syncthreads();

    float e0[4];
    e0[0] = __expf(v0.x - m); e0[1] = __expf(v0.y - m);
    e0[2] = __expf(v0.z - m); e0[3] = __expf(v0.w - m);
    float e1[4];
#pragma unroll
    for (int l = 0; l < 4; l++)
        e1[l] = (b1 + l <= t) ? __expf(vv[l] - m) : 0.f;

    float s = e0[0] + e0[1] + e0[2] + e0[3] + e1[0] + e1[1] + e1[2] + e1[3];
    red[tx] = s; __syncthreads();
    for (int st = 128; st > 0; st >>= 1) {
        if (tx < st) red[tx] += red[tx + st];
        __syncthreads();
    }
    const float inv = 1.f / red[0];

    __nv_bfloat16* ah = g_ah + (size_t)row * 2048;
    __nv_bfloat16* al = g_al + (size_t)row * 2048;
    float o[8] = {e0[0] * inv, e0[1] * inv, e0[2] * inv, e0[3] * inv,
                  e1[0] * inv, e1[1] * inv, e1[2] * inv, e1[3] * inv};
#pragma unroll
    for (int g = 0; g < 2; g++) {
        int off = (g == 0) ? b1 : 1024 + b1;
#pragma unroll
        for (int c = 0; c < 4; c += 2) {
            __nv_bfloat16 h0, h1, l0, l1;
            split2(o[g * 4 + c], h0, l0); split2(o[g * 4 + c + 1], h1, l1);
            __nv_bfloat162 H; H.x = h0; H.y = h1;
            __nv_bfloat162 L; L.x = l0; L.y = l1;
            *(__nv_bfloat162*)(ah + off + c) = H;
            *(__nv_bfloat162*)(al + off + c) = L;
        }
    }
}

// ---------------------------------------------------------------------------
// PV: O[bh,t,d] = att . vT  -> split bf16 in [B,T,C] layout
// ---------------------------------------------------------------------------
__global__ void __launch_bounds__(256) pv_mma()
{
    __shared__ __align__(1024) char smem[32768];
    const int bh = blockIdx.z;
    const int m0 = blockIdx.y * 128;         // t
    const int NC = (1152 + m0) / 32;         // trailing zero K-chunks skipped

    Frag F;
    mma_mainloop(smem,
        g_ah  + ((size_t)bh * TT + m0) * TOTL, g_al  + ((size_t)bh * TT + m0) * TOTL,
        g_vth + (size_t)bh * DD * TOTL,        g_vtl + (size_t)bh * DD * TOTL,
        TOTL, TOTL, NC, F);

    const int lane = threadIdx.x & 31, wid = threadIdx.x >> 5;
    const int wm = wid & 3, wn = wid >> 2;
    const int b = bh >> 4, h = bh & 15;
#pragma unroll
    for (int mt = 0; mt < 2; mt++)
#pragma unroll
        for (int half = 0; half < 2; half++) {
            int t = m0 + wm * 32 + mt * 16 + lane / 4 + half * 8;
            size_t base = ((size_t)(b * 1024 + t)) * 2048 + h * 128;
#pragma unroll
            for (int nt = 0; nt < 8; nt++) {
                int d = wn * 64 + nt * 8 + (lane & 3) * 2;
                float v0 = F.c[mt][nt][half * 2], v1 = F.c[mt][nt][half * 2 + 1];
                __nv_bfloat16 h0, h1, l0, l1;
                split2(v0, h0, l0); split2(v1, h1, l1);
                __nv_bfloat162 H; H.x = h0; H.y = h1;
                __nv_bfloat162 L; L.x = l0; L.y = l1;
                *(__nv_bfloat162*)(g_aoh + base + d) = H;
                *(__nv_bfloat162*)(g_aol + base + d) = L;
            }
        }
}

// ---------------------------------------------------------------------------
// Output projection: out = ao @ Wp^T + bp
// ---------------------------------------------------------------------------
__global__ void __launch_bounds__(256) proj_mma(const float* __restrict__ bp,
                                                float* __restrict__ out)
{
    __shared__ __align__(1024) char smem[32768];
    const int m0 = blockIdx.y * 128, n0 = blockIdx.x * 128;
    Frag F;
    mma_mainloop(smem,
        g_aoh + (size_t)m0 * CC, g_aol + (size_t)m0 * CC,
        g_wph + (size_t)n0 * CC, g_wpl + (size_t)n0 * CC, CC, CC, 64, F);

    const int lane = threadIdx.x & 31, wid = threadIdx.x >> 5;
    const int wm = wid & 3, wn = wid >> 2;
#pragma unroll
    for (int mt = 0; mt < 2; mt++)
#pragma unroll
        for (int half = 0; half < 2; half++) {
            int m = m0 + wm * 32 + mt * 16 + lane / 4 + half * 8;
#pragma unroll
            for (int nt = 0; nt < 8; nt++) {
                int n = n0 + wn * 64 + nt * 8 + (lane & 3) * 2;
                float2 bias = *(const float2*)(bp + n);
                *(float2*)(out + (size_t)m * 2048 + n) =
                    make_float2(F.c[mt][nt][half * 2] + bias.x,
                                F.c[mt][nt][half * 2 + 1] + bias.y);
            }
        }
}

// ---------------------------------------------------------------------------
extern "C" void kernel_launch(void* const* d_in, const int* in_sizes, int n_in,
                              void* d_out, int out_size)
{
    (void)in_sizes; (void)n_in; (void)out_size;
    const float* x      = (const float*)d_in[0];
    const float* past_k = (const float*)d_in[1];
    const float* past_v = (const float*)d_in[2];
    const float* Wk     = (const float*)d_in[3];
    const float* Wq     = (const float*)d_in[4];
    const float* Wv     = (const float*)d_in[5];
    const float* Wp     = (const float*)d_in[6];
    const float* bp     = (const float*)d_in[7];

    float* out  = (float*)d_out;
    float* outk = out + (size_t)BB * TT * CC;
    float* outv = outk + (size_t)BHN * TOTL * DD;

    __nv_bfloat16 *xh, *xl, *wqh, *wql, *wkh, *wkl, *wvh, *wvl, *wph, *wpl, *kh, *kl;
    cudaGetSymbolAddress((void**)&xh,  g_xh);  cudaGetSymbolAddress((void**)&xl,  g_xl);
    cudaGetSymbolAddress((void**)&wqh, g_wqh); cudaGetSymbolAddress((void**)&wql, g_wql);
    cudaGetSymbolAddress((void**)&wkh, g_wkh); cudaGetSymbolAddress((void**)&wkl, g_wkl);
    cudaGetSymbolAddress((void**)&wvh, g_wvh); cudaGetSymbolAddress((void**)&wvl, g_wvl);
    cudaGetSymbolAddress((void**)&wph, g_wph); cudaGetSymbolAddress((void**)&wpl, g_wpl);
    cudaGetSymbolAddress((void**)&kh,  g_kh);  cudaGetSymbolAddress((void**)&kl,  g_kl);

    const int n4w = CC * CC / 4;
    const int nb  = (n4w + 255) / 256;

    // 1. split fp32 inputs into bf16 hi/lo
    split_kernel<<<nb, 256>>>((const float4*)x,  (__nv_bfloat162*)xh,  (__nv_bfloat162*)xl,  n4w);
    split_kernel<<<nb, 256>>>((const float4*)Wq, (__nv_bfloat162*)wqh, (__nv_bfloat162*)wql, n4w);
    split_kernel<<<nb, 256>>>((const float4*)Wk, (__nv_bfloat162*)wkh, (__nv_bfloat162*)wkl, n4w);
    split_kernel<<<nb, 256>>>((const float4*)Wv, (__nv_bfloat162*)wvh, (__nv_bfloat162*)wvl, n4w);
    split_kernel<<<nb, 256>>>((const float4*)Wp, (__nv_bfloat162*)wph, (__nv_bfloat162*)wpl, n4w);

    // 2. past KV -> fp32 cache
    copy_past_kernel<<<8192, 256>>>((const float4*)past_k, (const float4*)past_v,
                                    (float4*)outk, (float4*)outv);

    // 3. QKV projection (tensor pipe)
    qkv_mma<<<dim3(16, 16, 3), 256>>>(outk, outv);

    // 4. split K cache; transpose+split V cache
    const int n4k = BHN * TOTL * DD / 4;
    split_kernel<<<(n4k + 255) / 256, 256>>>((const float4*)outk,
                                             (__nv_bfloat162*)kh, (__nv_bfloat162*)kl, n4k);
    vtrans_kernel<<<dim3(64, 4, 32), 256>>>(outv);

    // 5. attention scores (tensor pipe)
    scores_mma<<<dim3(16, 8, 32), 256>>>();

    // 6. masked softmax -> split bf16 probabilities
    softmax_kernel<<<32768, 256>>>();

    // 7. P @ V (tensor pipe)
    pv_mma<<<dim3(1, 8, 32), 256>>>();

    // 8. output projection + bias (tensor pipe)
    proj_mma<<<dim3(16, 16), 256>>>(bp, out);
}

// round 6
// speedup vs baseline: 4.1436x; 1.1644x over previous
#include <cuda_runtime.h>
#include <cuda_bf16.h>
#include <math.h>
#include <stdint.h>

// Problem constants
#define BB   2
#define TT   1024
#define CC   2048
#define HH   16
#define DD   128
#define PP   1024
#define TOTL 2048
#define BHN  32

#define STAGE_BYTES 32768
#define NSTAGE      3
#define DSMEM       (NSTAGE * STAGE_BYTES)   // 96 KB dynamic smem

// ---------------------------------------------------------------------------
// Device scratch (allocation-free)
// ---------------------------------------------------------------------------
__device__ float         g_att[(size_t)BHN * TT * TOTL];      // fp32 scores
__device__ __nv_bfloat16 g_xh [(size_t)CC * CC], g_xl [(size_t)CC * CC];
__device__ __nv_bfloat16 g_wqh[(size_t)CC * CC], g_wql[(size_t)CC * CC];
__device__ __nv_bfloat16 g_wkh[(size_t)CC * CC], g_wkl[(size_t)CC * CC];
__device__ __nv_bfloat16 g_wvh[(size_t)CC * CC], g_wvl[(size_t)CC * CC];
__device__ __nv_bfloat16 g_wph[(size_t)CC * CC], g_wpl[(size_t)CC * CC];
__device__ __nv_bfloat16 g_qh [(size_t)BHN * TT * DD],   g_ql [(size_t)BHN * TT * DD];
__device__ __nv_bfloat16 g_kh [(size_t)BHN * TOTL * DD], g_kl [(size_t)BHN * TOTL * DD];
__device__ __nv_bfloat16 g_vth[(size_t)BHN * DD * TOTL], g_vtl[(size_t)BHN * DD * TOTL];
__device__ __nv_bfloat16 g_ah [(size_t)BHN * TT * TOTL], g_al [(size_t)BHN * TT * TOTL];
__device__ __nv_bfloat16 g_aoh[(size_t)BB * TT * CC],    g_aol[(size_t)BB * TT * CC];

__device__ __forceinline__ uint32_t smem_u32(const void* p) {
    uint32_t a;
    asm("{ .reg .u64 t; cvta.to.shared.u64 t, %1; cvt.u32.u64 %0, t; }" : "=r"(a) : "l"(p));
    return a;
}
__device__ __forceinline__ void split2(float v, __nv_bfloat16& h, __nv_bfloat16& l) {
    h = __float2bfloat16(v);
    l = __float2bfloat16(v - __bfloat162float(h));
}
__device__ __forceinline__ void cpasync16(uint32_t dst, const void* src) {
    asm volatile("cp.async.cg.shared.global [%0], [%1], 16;" :: "r"(dst), "l"(src));
}
#define CP_COMMIT() asm volatile("cp.async.commit_group;" ::: "memory")
#define CP_WAIT1()  asm volatile("cp.async.wait_group 1;"  ::: "memory")

#define LDM4(r, addr)                                                        \
    asm volatile("ldmatrix.sync.aligned.m8n8.x4.shared.b16 {%0,%1,%2,%3}, [%4];" \
        : "=r"((r)[0]), "=r"((r)[1]), "=r"((r)[2]), "=r"((r)[3]) : "r"(addr))

#define MMA16816(c, a, b0v, b1v)                                             \
    asm volatile("mma.sync.aligned.m16n8k16.row.col.f32.bf16.bf16.f32 "      \
        "{%0,%1,%2,%3}, {%4,%5,%6,%7}, {%8,%9}, {%0,%1,%2,%3};"              \
        : "+f"((c)[0]), "+f"((c)[1]), "+f"((c)[2]), "+f"((c)[3])             \
        : "r"((a)[0]), "r"((a)[1]), "r"((a)[2]), "r"((a)[3]),                \
          "r"(b0v), "r"(b1v))

// swizzle for 64B rows (32 bf16): conflict-free ldmatrix + cp.async stores
__device__ __forceinline__ uint32_t swz(uint32_t o) { return o ^ ((o >> 3) & 0x30); }

// ---------------------------------------------------------------------------
// Warp-MMA mainloop, 3-stage cp.async ring.
// CTA 256 thr = 8 warps (4x2). CTA tile 128(m) x 128(n), K-chunk 32.
// A = Ah+Al [m,k] row-major; B = Bh+Bl [n,k] row-major (NT GEMM).
// 3-term: C = AhBh + AhBl + AlBh, fp32 accumulators.
// Stage layout: Ah @0, Al @8K, Bh @16K, Bl @24K (128x32 bf16 tiles).
// ---------------------------------------------------------------------------
struct Frag { float c[2][8][4]; };

__device__ __forceinline__ void mma_mainloop(
    char* smem,
    const __nv_bfloat16* __restrict__ Ah, const __nv_bfloat16* __restrict__ Al,
    const __nv_bfloat16* __restrict__ Bh, const __nv_bfloat16* __restrict__ Bl,
    size_t ldA, size_t ldB, int NC, Frag& F)
{
    const uint32_t sb = smem_u32(smem);
    const int tid  = threadIdx.x;
    const int lane = tid & 31;
    const int wid  = tid >> 5;
    const int wm   = wid & 3;
    const int wn   = wid >> 2;

#pragma unroll
    for (int i = 0; i < 2; i++)
#pragma unroll
        for (int j = 0; j < 8; j++)
#pragma unroll
            for (int k = 0; k < 4; k++) F.c[i][j][k] = 0.f;

    // per-thread cp.async streams: 8 x 16B per chunk
    const __nv_bfloat16* gp[8];
    uint32_t soff[8];
#pragma unroll
    for (int j = 0; j < 8; j++) {
        int u = tid + 256 * (j & 1);
        int row = u >> 2, un = u & 3, T = j >> 1;
        const __nv_bfloat16* base = (T == 0) ? Ah : (T == 1) ? Al : (T == 2) ? Bh : Bl;
        size_t ld = (T < 2) ? ldA : ldB;
        gp[j]   = base + (size_t)row * ld + un * 8;
        soff[j] = T * 8192 + swz(row * 64 + un * 16);
    }

    // fragment smem offsets (tile-relative, swizzled)
    uint32_t aoff[2][2], boff[4][2];
#pragma unroll
    for (int mt = 0; mt < 2; mt++)
#pragma unroll
        for (int kk = 0; kk < 2; kk++) {
            int row = wm * 32 + mt * 16 + (lane & 15);
            aoff[mt][kk] = swz(row * 64 + kk * 32 + ((lane >> 4) & 1) * 16);
        }
#pragma unroll
    for (int bt = 0; bt < 4; bt++)
#pragma unroll
        for (int kk = 0; kk < 2; kk++) {
            int row = wn * 64 + bt * 16 + (lane & 7) + ((lane >> 4) & 1) * 8;
            boff[bt][kk] = swz(row * 64 + kk * 32 + ((lane >> 3) & 1) * 16);
        }

    // prologue: chunks 0,1 -> stages 0,1
#pragma unroll
    for (int p = 0; p < 2; p++) {
        if (p < NC) {
            uint32_t st = sb + p * STAGE_BYTES;
#pragma unroll
            for (int j = 0; j < 8; j++)
                cpasync16(st + soff[j], gp[j] + (size_t)p * 32);
        }
        CP_COMMIT();
    }

    int stage = 0;
    for (int ch = 0; ch < NC; ch++) {
        CP_WAIT1();
        __syncthreads();

        const int pf = ch + 2;
        if (pf < NC) {
            int pstage = stage + 2; if (pstage >= NSTAGE) pstage -= NSTAGE;
            uint32_t st = sb + pstage * STAGE_BYTES;
#pragma unroll
            for (int j = 0; j < 8; j++)
                cpasync16(st + soff[j], gp[j] + (size_t)pf * 32);
        }
        CP_COMMIT();

        const uint32_t stb = sb + stage * STAGE_BYTES;
#pragma unroll
        for (int kk = 0; kk < 2; kk++) {
            uint32_t ah[2][4], al[2][4], bh4[4][4], bl4[4][4];
#pragma unroll
            for (int mt = 0; mt < 2; mt++) LDM4(ah[mt], stb + aoff[mt][kk]);
#pragma unroll
            for (int bt = 0; bt < 4; bt++) LDM4(bh4[bt], stb + 16384 + boff[bt][kk]);
#pragma unroll
            for (int mt = 0; mt < 2; mt++)
#pragma unroll
                for (int bt = 0; bt < 4; bt++) {
                    MMA16816(F.c[mt][bt * 2 + 0], ah[mt], bh4[bt][0], bh4[bt][1]);
                    MMA16816(F.c[mt][bt * 2 + 1], ah[mt], bh4[bt][2], bh4[bt][3]);
                }
#pragma unroll
            for (int bt = 0; bt < 4; bt++) LDM4(bl4[bt], stb + 24576 + boff[bt][kk]);
#pragma unroll
            for (int mt = 0; mt < 2; mt++)
#pragma unroll
                for (int bt = 0; bt < 4; bt++) {
                    MMA16816(F.c[mt][bt * 2 + 0], ah[mt], bl4[bt][0], bl4[bt][1]);
                    MMA16816(F.c[mt][bt * 2 + 1], ah[mt], bl4[bt][2], bl4[bt][3]);
                }
#pragma unroll
            for (int mt = 0; mt < 2; mt++) LDM4(al[mt], stb + 8192 + aoff[mt][kk]);
#pragma unroll
            for (int mt = 0; mt < 2; mt++)
#pragma unroll
                for (int bt = 0; bt < 4; bt++) {
                    MMA16816(F.c[mt][bt * 2 + 0], al[mt], bh4[bt][0], bh4[bt][1]);
                    MMA16816(F.c[mt][bt * 2 + 1], al[mt], bh4[bt][2], bh4[bt][3]);
                }
        }
        if (++stage == NSTAGE) stage = 0;
    }
}

// ---------------------------------------------------------------------------
// Conversion + aux kernels
// ---------------------------------------------------------------------------
__global__ void __launch_bounds__(256) split_kernel(
    const float4* __restrict__ src, __nv_bfloat162* __restrict__ dh,
    __nv_bfloat162* __restrict__ dl, int n4)
{
    int i = blockIdx.x * blockDim.x + threadIdx.x;
    if (i >= n4) return;
    float4 v = src[i];
    __nv_bfloat16 h0, h1, h2, h3, l0, l1, l2, l3;
    split2(v.x, h0, l0); split2(v.y, h1, l1);
    split2(v.z, h2, l2); split2(v.w, h3, l3);
    __nv_bfloat162 H0; H0.x = h0; H0.y = h1;
    __nv_bfloat162 H1; H1.x = h2; H1.y = h3;
    __nv_bfloat162 L0; L0.x = l0; L0.y = l1;
    __nv_bfloat162 L1; L1.x = l2; L1.y = l3;
    dh[2 * i] = H0; dh[2 * i + 1] = H1;
    dl[2 * i] = L0; dl[2 * i + 1] = L1;
}

// v[bh][j][d] fp32 -> vt hi/lo [bh][d][j] bf16
__global__ void __launch_bounds__(256) vtrans_kernel(const float* __restrict__ v)
{
    __shared__ float tile[32][33];
    const int bh = blockIdx.z;
    const int j0 = blockIdx.x * 32, d0 = blockIdx.y * 32;
    const int tx = threadIdx.x & 31, ty = threadIdx.x >> 5;
    const float* src = v + (size_t)bh * TOTL * DD;
#pragma unroll
    for (int i = 0; i < 4; i++)
        tile[ty + i * 8][tx] = src[(size_t)(j0 + ty + i * 8) * DD + d0 + tx];
    __syncthreads();
    __nv_bfloat16* dh = g_vth + (size_t)bh * DD * TOTL;
    __nv_bfloat16* dl = g_vtl + (size_t)bh * DD * TOTL;
#pragma unroll
    for (int i = 0; i < 4; i++) {
        int d = d0 + ty + i * 8, j = j0 + tx;
        float val = tile[tx][ty + i * 8];
        __nv_bfloat16 h, l; split2(val, h, l);
        dh[(size_t)d * TOTL + j] = h;
        dl[(size_t)d * TOTL + j] = l;
    }
}

// past KV -> fp32 cache rows [0,1024); K also split to g_kh/g_kl
__global__ void copy_past_kernel(const float4* __restrict__ pk,
                                 const float4* __restrict__ pv,
                                 float4* __restrict__ outk,
                                 float4* __restrict__ outv)
{
    const int n4 = BB * HH * PP * DD / 4;
    int idx = blockIdx.x * blockDim.x + threadIdx.x;
    if (idx >= 2 * n4) return;
    if (idx < n4) {
        int bh = idx >> 15, rem = idx & 32767;
        size_t d4 = (size_t)bh * (TOTL * DD / 4) + rem;
        float4 v = pk[idx];
        outk[d4] = v;
        __nv_bfloat16 h0, h1, h2, h3, l0, l1, l2, l3;
        split2(v.x, h0, l0); split2(v.y, h1, l1);
        split2(v.z, h2, l2); split2(v.w, h3, l3);
        __nv_bfloat162 H0; H0.x = h0; H0.y = h1;
        __nv_bfloat162 H1; H1.x = h2; H1.y = h3;
        __nv_bfloat162 L0; L0.x = l0; L0.y = l1;
        __nv_bfloat162 L1; L1.x = l2; L1.y = l3;
        ((__nv_bfloat162*)g_kh)[2 * d4]     = H0;
        ((__nv_bfloat162*)g_kh)[2 * d4 + 1] = H1;
        ((__nv_bfloat162*)g_kl)[2 * d4]     = L0;
        ((__nv_bfloat162*)g_kl)[2 * d4 + 1] = L1;
    } else {
        int i = idx - n4;
        int bh = i >> 15, rem = i & 32767;
        outv[(size_t)bh * (TOTL * DD / 4) + rem] = pv[i];
    }
}

// ---------------------------------------------------------------------------
// QKV projection: y = x @ W^T, z selects {Wq, Wk, Wv}
// ---------------------------------------------------------------------------
__global__ void __launch_bounds__(256) qkv_mma(float* __restrict__ outk,
                                               float* __restrict__ outv)
{
    extern __shared__ __align__(1024) char smem[];
    const int z = blockIdx.z;
    const int m0 = blockIdx.y * 128, n0 = blockIdx.x * 128;
    const __nv_bfloat16* Bh = (z == 0) ? g_wqh : (z == 1) ? g_wkh : g_wvh;
    const __nv_bfloat16* Bl = (z == 0) ? g_wql : (z == 1) ? g_wkl : g_wvl;
    Frag F;
    mma_mainloop(smem,
        g_xh + (size_t)m0 * CC, g_xl + (size_t)m0 * CC,
        Bh + (size_t)n0 * CC,   Bl + (size_t)n0 * CC, CC, CC, 64, F);

    const int lane = threadIdx.x & 31, wid = threadIdx.x >> 5;
    const int wm = wid & 3, wn = wid >> 2;
#pragma unroll
    for (int mt = 0; mt < 2; mt++)
#pragma unroll
        for (int half = 0; half < 2; half++) {
            int m = m0 + wm * 32 + mt * 16 + lane / 4 + half * 8;
            int b = m >> 10, t = m & 1023;
#pragma unroll
            for (int nt = 0; nt < 8; nt++) {
                int n = n0 + wn * 64 + nt * 8 + (lane & 3) * 2;
                int h = n >> 7, d = n & 127;
                float v0 = F.c[mt][nt][half * 2], v1 = F.c[mt][nt][half * 2 + 1];
                if (z == 0) {
                    size_t base = (((size_t)(b * 16 + h)) * 1024 + t) * 128 + d;
                    __nv_bfloat16 h0, h1, l0, l1;
                    split2(v0, h0, l0); split2(v1, h1, l1);
                    __nv_bfloat162 H; H.x = h0; H.y = h1;
                    __nv_bfloat162 L; L.x = l0; L.y = l1;
                    *(__nv_bfloat162*)(g_qh + base) = H;
                    *(__nv_bfloat162*)(g_ql + base) = L;
                } else if (z == 1) {
                    size_t base = (((size_t)(b * 16 + h)) * 2048 + 1024 + t) * 128 + d;
                    *(float2*)(outk + base) = make_float2(v0, v1);
                    __nv_bfloat16 h0, h1, l0, l1;
                    split2(v0, h0, l0); split2(v1, h1, l1);
                    __nv_bfloat162 H; H.x = h0; H.y = h1;
                    __nv_bfloat162 L; L.x = l0; L.y = l1;
                    *(__nv_bfloat162*)(g_kh + base) = H;
                    *(__nv_bfloat162*)(g_kl + base) = L;
                } else {
                    size_t base = (((size_t)(b * 16 + h)) * 2048 + 1024 + t) * 128 + d;
                    *(float2*)(outv + base) = make_float2(v0, v1);
                }
            }
        }
}

// ---------------------------------------------------------------------------
// Scores: S[bh,t,j] = scale * q . k   (fully-masked tiles skipped)
// ---------------------------------------------------------------------------
__global__ void __launch_bounds__(256) scores_mma()
{
    extern __shared__ __align__(1024) char smem[];
    const int bh = blockIdx.z;
    const int m0 = blockIdx.y * 128;
    const int n0 = blockIdx.x * 128;
    if (n0 > 1151 + m0) return;

    Frag F;
    mma_mainloop(smem,
        g_qh + ((size_t)bh * TT + m0) * DD,   g_ql + ((size_t)bh * TT + m0) * DD,
        g_kh + ((size_t)bh * TOTL + n0) * DD, g_kl + ((size_t)bh * TOTL + n0) * DD,
        DD, DD, 4, F);

    const int lane = threadIdx.x & 31, wid = threadIdx.x >> 5;
    const int wm = wid & 3, wn = wid >> 2;
    const float scale = 0.08838834764831845f;
#pragma unroll
    for (int mt = 0; mt < 2; mt++)
#pragma unroll
        for (int half = 0; half < 2; half++) {
            int t = m0 + wm * 32 + mt * 16 + lane / 4 + half * 8;
            float* dst = g_att + ((size_t)bh * TT + t) * TOTL;
#pragma unroll
            for (int nt = 0; nt < 8; nt++) {
                int n = n0 + wn * 64 + nt * 8 + (lane & 3) * 2;
                *(float2*)(dst + n) = make_float2(F.c[mt][nt][half * 2] * scale,
                                                  F.c[mt][nt][half * 2 + 1] * scale);
            }
        }
}

// ---------------------------------------------------------------------------
// Masked softmax: fp32 g_att -> split bf16 g_ah/g_al (masked = 0)
// ---------------------------------------------------------------------------
__global__ void __launch_bounds__(256) softmax_kernel()
{
    __shared__ float red[256];
    const int row = blockIdx.x;
    const int t = row & 1023;
    const float4* p4 = (const float4*)(g_att + (size_t)row * 2048);
    const int tx = threadIdx.x;

    float4 v0 = p4[tx];
    float4 v1 = p4[tx + 256];
    const int b1 = tx * 4;
    float vv[4] = {v1.x, v1.y, v1.z, v1.w};

    float m = fmaxf(fmaxf(v0.x, v0.y), fmaxf(v0.z, v0.w));
#pragma unroll
    for (int l = 0; l < 4; l++)
        if (b1 + l <= t) m = fmaxf(m, vv[l]);

    red[tx] = m; __syncthreads();
    for (int s = 128; s > 0; s >>= 1) {
        if (tx < s) red[tx] = fmaxf(red[tx], red[tx + s]);
        __syncthreads();
    }
    m = red[0];
    __syncthreads();

    float e0[4];
    e0[0] = __expf(v0.x - m); e0[1] = __expf(v0.y - m);
    e0[2] = __expf(v0.z - m); e0[3] = __expf(v0.w - m);
    float e1[4];
#pragma unroll
    for (int l = 0; l < 4; l++)
        e1[l] = (b1 + l <= t) ? __expf(vv[l] - m) : 0.f;

    float s = e0[0] + e0[1] + e0[2] + e0[3] + e1[0] + e1[1] + e1[2] + e1[3];
    red[tx] = s; __syncthreads();
    for (int st = 128; st > 0; st >>= 1) {
        if (tx < st) red[tx] += red[tx + st];
        __syncthreads();
    }
    const float inv = 1.f / red[0];

    __nv_bfloat16* ah = g_ah + (size_t)row * 2048;
    __nv_bfloat16* al = g_al + (size_t)row * 2048;
    float o[8] = {e0[0] * inv, e0[1] * inv, e0[2] * inv, e0[3] * inv,
                  e1[0] * inv, e1[1] * inv, e1[2] * inv, e1[3] * inv};
#pragma unroll
    for (int g = 0; g < 2; g++) {
        int off = (g == 0) ? b1 : 1024 + b1;
#pragma unroll
        for (int c = 0; c < 4; c += 2) {
            __nv_bfloat16 h0, h1, l0, l1;
            split2(o[g * 4 + c], h0, l0); split2(o[g * 4 + c + 1], h1, l1);
            __nv_bfloat162 H; H.x = h0; H.y = h1;
            __nv_bfloat162 L; L.x = l0; L.y = l1;
            *(__nv_bfloat162*)(ah + off + c) = H;
            *(__nv_bfloat162*)(al + off + c) = L;
        }
    }
}

// ---------------------------------------------------------------------------
// PV: O[bh,t,d] = att . vT  -> split bf16 in [B,T,C] layout
// ---------------------------------------------------------------------------
__global__ void __launch_bounds__(256) pv_mma()
{
    extern __shared__ __align__(1024) char smem[];
    const int bh = blockIdx.z;
    const int m0 = blockIdx.y * 128;
    const int NC = (1152 + m0) / 32;

    Frag F;
    mma_mainloop(smem,
        g_ah  + ((size_t)bh * TT + m0) * TOTL, g_al  + ((size_t)bh * TT + m0) * TOTL,
        g_vth + (size_t)bh * DD * TOTL,        g_vtl + (size_t)bh * DD * TOTL,
        TOTL, TOTL, NC, F);

    const int lane = threadIdx.x & 31, wid = threadIdx.x >> 5;
    const int wm = wid & 3, wn = wid >> 2;
    const int b = bh >> 4, h = bh & 15;
#pragma unroll
    for (int mt = 0; mt < 2; mt++)
#pragma unroll
        for (int half = 0; half < 2; half++) {
            int t = m0 + wm * 32 + mt * 16 + lane / 4 + half * 8;
            size_t base = ((size_t)(b * 1024 + t)) * 2048 + h * 128;
#pragma unroll
            for (int nt = 0; nt < 8; nt++) {
                int d = wn * 64 + nt * 8 + (lane & 3) * 2;
                float v0 = F.c[mt][nt][half * 2], v1 = F.c[mt][nt][half * 2 + 1];
                __nv_bfloat16 h0, h1, l0, l1;
                split2(v0, h0, l0); split2(v1, h1, l1);
                __nv_bfloat162 H; H.x = h0; H.y = h1;
                __nv_bfloat162 L; L.x = l0; L.y = l1;
                *(__nv_bfloat162*)(g_aoh + base + d) = H;
                *(__nv_bfloat162*)(g_aol + base + d) = L;
            }
        }
}

// ---------------------------------------------------------------------------
// Output projection: out = ao @ Wp^T + bp
// ---------------------------------------------------------------------------
__global__ void __launch_bounds__(256) proj_mma(const float* __restrict__ bp,
                                                float* __restrict__ out)
{
    extern __shared__ __align__(1024) char smem[];
    const int m0 = blockIdx.y * 128, n0 = blockIdx.x * 128;
    Frag F;
    mma_mainloop(smem,
        g_aoh + (size_t)m0 * CC, g_aol + (size_t)m0 * CC,
        g_wph + (size_t)n0 * CC, g_wpl + (size_t)n0 * CC, CC, CC, 64, F);

    const int lane = threadIdx.x & 31, wid = threadIdx.x >> 5;
    const int wm = wid & 3, wn = wid >> 2;
#pragma unroll
    for (int mt = 0; mt < 2; mt++)
#pragma unroll
        for (int half = 0; half < 2; half++) {
            int m = m0 + wm * 32 + mt * 16 + lane / 4 + half * 8;
#pragma unroll
            for (int nt = 0; nt < 8; nt++) {
                int n = n0 + wn * 64 + nt * 8 + (lane & 3) * 2;
                float2 bias = *(const float2*)(bp + n);
                *(float2*)(out + (size_t)m * 2048 + n) =
                    make_float2(F.c[mt][nt][half * 2] + bias.x,
                                F.c[mt][nt][half * 2 + 1] + bias.y);
            }
        }
}

// ---------------------------------------------------------------------------
extern "C" void kernel_launch(void* const* d_in, const int* in_sizes, int n_in,
                              void* d_out, int out_size)
{
    (void)in_sizes; (void)n_in; (void)out_size;
    const float* x      = (const float*)d_in[0];
    const float* past_k = (const float*)d_in[1];
    const float* past_v = (const float*)d_in[2];
    const float* Wk     = (const float*)d_in[3];
    const float* Wq     = (const float*)d_in[4];
    const float* Wv     = (const float*)d_in[5];
    const float* Wp     = (const float*)d_in[6];
    const float* bp     = (const float*)d_in[7];

    float* out  = (float*)d_out;
    float* outk = out + (size_t)BB * TT * CC;
    float* outv = outk + (size_t)BHN * TOTL * DD;

    cudaFuncSetAttribute(qkv_mma,    cudaFuncAttributeMaxDynamicSharedMemorySize, DSMEM);
    cudaFuncSetAttribute(scores_mma, cudaFuncAttributeMaxDynamicSharedMemorySize, DSMEM);
    cudaFuncSetAttribute(pv_mma,     cudaFuncAttributeMaxDynamicSharedMemorySize, DSMEM);
    cudaFuncSetAttribute(proj_mma,   cudaFuncAttributeMaxDynamicSharedMemorySize, DSMEM);

    __nv_bfloat16 *xh, *xl, *wqh, *wql, *wkh, *wkl, *wvh, *wvl, *wph, *wpl;
    cudaGetSymbolAddress((void**)&xh,  g_xh);  cudaGetSymbolAddress((void**)&xl,  g_xl);
    cudaGetSymbolAddress((void**)&wqh, g_wqh); cudaGetSymbolAddress((void**)&wql, g_wql);
    cudaGetSymbolAddress((void**)&wkh, g_wkh); cudaGetSymbolAddress((void**)&wkl, g_wkl);
    cudaGetSymbolAddress((void**)&wvh, g_wvh); cudaGetSymbolAddress((void**)&wvl, g_wvl);
    cudaGetSymbolAddress((void**)&wph, g_wph); cudaGetSymbolAddress((void**)&wpl, g_wpl);

    const int n4w = CC * CC / 4;
    const int nb  = (n4w + 255) / 256;

    // 1. split fp32 inputs into bf16 hi/lo
    split_kernel<<<nb, 256>>>((const float4*)x,  (__nv_bfloat162*)xh,  (__nv_bfloat162*)xl,  n4w);
    split_kernel<<<nb, 256>>>((const float4*)Wq, (__nv_bfloat162*)wqh, (__nv_bfloat162*)wql, n4w);
    split_kernel<<<nb, 256>>>((const float4*)Wk, (__nv_bfloat162*)wkh, (__nv_bfloat162*)wkl, n4w);
    split_kernel<<<nb, 256>>>((const float4*)Wv, (__nv_bfloat162*)wvh, (__nv_bfloat162*)wvl, n4w);
    split_kernel<<<nb, 256>>>((const float4*)Wp, (__nv_bfloat162*)wph, (__nv_bfloat162*)wpl, n4w);

    // 2. past KV -> fp32 cache (K also split to bf16 hi/lo)
    copy_past_kernel<<<8192, 256>>>((const float4*)past_k, (const float4*)past_v,
                                    (float4*)outk, (float4*)outv);

    // 3. QKV projection (writes fp32 caches + split Q/K)
    qkv_mma<<<dim3(16, 16, 3), 256, DSMEM>>>(outk, outv);

    // 4. transpose+split V cache
    vtrans_kernel<<<dim3(64, 4, 32), 256>>>(outv);

    // 5. attention scores
    scores_mma<<<dim3(16, 8, 32), 256, DSMEM>>>();

    // 6. masked softmax -> split bf16 probabilities
    softmax_kernel<<<32768, 256>>>();

    // 7. P @ V
    pv_mma<<<dim3(1, 8, 32), 256, DSMEM>>>();

    // 8. output projection + bias
    proj_mma<<<dim3(16, 16), 256, DSMEM>>>(bp, out);
}

// round 7
// speedup vs baseline: 4.5194x; 1.0907x over previous
#include <cuda_runtime.h>
#include <cuda_bf16.h>
#include <math.h>
#include <stdint.h>

// Problem constants
#define BB   2
#define TT   1024
#define CC   2048
#define HH   16
#define DD   128
#define PP   1024
#define TOTL 2048
#define BHN  32

#define STAGE_BYTES 32768
#define NSTAGE      3
#define DSMEM       (NSTAGE * STAGE_BYTES)   // 96 KB (qkv/proj GEMMs)

// flash kernel smem
#define FL_STAGE  16384
#define FL_NST    3
#define FL_QOFF   (FL_NST * FL_STAGE)        // 49152
#define FL_DSMEM  (FL_QOFF + 65536)          // 114688

// ---------------------------------------------------------------------------
// Device scratch (allocation-free)
// ---------------------------------------------------------------------------
__device__ __nv_bfloat16 g_xh [(size_t)CC * CC], g_xl [(size_t)CC * CC];
__device__ __nv_bfloat16 g_wqh[(size_t)CC * CC], g_wql[(size_t)CC * CC];
__device__ __nv_bfloat16 g_wkh[(size_t)CC * CC], g_wkl[(size_t)CC * CC];
__device__ __nv_bfloat16 g_wvh[(size_t)CC * CC], g_wvl[(size_t)CC * CC];
__device__ __nv_bfloat16 g_wph[(size_t)CC * CC], g_wpl[(size_t)CC * CC];
__device__ __nv_bfloat16 g_qh [(size_t)BHN * TT * DD],   g_ql [(size_t)BHN * TT * DD];
__device__ __nv_bfloat16 g_kh [(size_t)BHN * TOTL * DD], g_kl [(size_t)BHN * TOTL * DD];
__device__ __nv_bfloat16 g_vth[(size_t)BHN * DD * TOTL], g_vtl[(size_t)BHN * DD * TOTL];
__device__ __nv_bfloat16 g_aoh[(size_t)BB * TT * CC],    g_aol[(size_t)BB * TT * CC];

__device__ __forceinline__ uint32_t smem_u32(const void* p) {
    uint32_t a;
    asm("{ .reg .u64 t; cvta.to.shared.u64 t, %1; cvt.u32.u64 %0, t; }" : "=r"(a) : "l"(p));
    return a;
}
__device__ __forceinline__ void split2(float v, __nv_bfloat16& h, __nv_bfloat16& l) {
    h = __float2bfloat16(v);
    l = __float2bfloat16(v - __bfloat162float(h));
}
__device__ __forceinline__ uint32_t packbf(__nv_bfloat16 a, __nv_bfloat16 b) {
    __nv_bfloat162 t; t.x = a; t.y = b;
    return *(uint32_t*)&t;
}
__device__ __forceinline__ void cpasync16(uint32_t dst, const void* src) {
    asm volatile("cp.async.cg.shared.global [%0], [%1], 16;" :: "r"(dst), "l"(src));
}
#define CP_COMMIT() asm volatile("cp.async.commit_group;" ::: "memory")
#define CP_WAIT1()  asm volatile("cp.async.wait_group 1;"  ::: "memory")

#define LDM4(r, addr)                                                        \
    asm volatile("ldmatrix.sync.aligned.m8n8.x4.shared.b16 {%0,%1,%2,%3}, [%4];" \
        : "=r"((r)[0]), "=r"((r)[1]), "=r"((r)[2]), "=r"((r)[3]) : "r"(addr))

#define MMA16816(c, a, b0v, b1v)                                             \
    asm volatile("mma.sync.aligned.m16n8k16.row.col.f32.bf16.bf16.f32 "      \
        "{%0,%1,%2,%3}, {%4,%5,%6,%7}, {%8,%9}, {%0,%1,%2,%3};"              \
        : "+f"((c)[0]), "+f"((c)[1]), "+f"((c)[2]), "+f"((c)[3])             \
        : "r"((a)[0]), "r"((a)[1]), "r"((a)[2]), "r"((a)[3]),                \
          "r"(b0v), "r"(b1v))

__device__ __forceinline__ uint32_t swz(uint32_t o) { return o ^ ((o >> 3) & 0x30); }

// ---------------------------------------------------------------------------
// Dense GEMM mainloop (qkv/proj): 3-stage cp.async ring, 8 warps 4x2,
// CTA 128x128, K-chunk 32, C = AhBh + AhBl + AlBh.
// ---------------------------------------------------------------------------
struct Frag { float c[2][8][4]; };

__device__ __forceinline__ void mma_mainloop(
    char* smem,
    const __nv_bfloat16* __restrict__ Ah, const __nv_bfloat16* __restrict__ Al,
    const __nv_bfloat16* __restrict__ Bh, const __nv_bfloat16* __restrict__ Bl,
    size_t ldA, size_t ldB, int NC, Frag& F)
{
    const uint32_t sb = smem_u32(smem);
    const int tid  = threadIdx.x;
    const int lane = tid & 31;
    const int wid  = tid >> 5;
    const int wm   = wid & 3;
    const int wn   = wid >> 2;

#pragma unroll
    for (int i = 0; i < 2; i++)
#pragma unroll
        for (int j = 0; j < 8; j++)
#pragma unroll
            for (int k = 0; k < 4; k++) F.c[i][j][k] = 0.f;

    const __nv_bfloat16* gp[8];
    uint32_t soff[8];
#pragma unroll
    for (int j = 0; j < 8; j++) {
        int u = tid + 256 * (j & 1);
        int row = u >> 2, un = u & 3, T = j >> 1;
        const __nv_bfloat16* base = (T == 0) ? Ah : (T == 1) ? Al : (T == 2) ? Bh : Bl;
        size_t ld = (T < 2) ? ldA : ldB;
        gp[j]   = base + (size_t)row * ld + un * 8;
        soff[j] = T * 8192 + swz(row * 64 + un * 16);
    }

    uint32_t aoff[2][2], boff[4][2];
#pragma unroll
    for (int mt = 0; mt < 2; mt++)
#pragma unroll
        for (int kk = 0; kk < 2; kk++) {
            int row = wm * 32 + mt * 16 + (lane & 15);
            aoff[mt][kk] = swz(row * 64 + kk * 32 + ((lane >> 4) & 1) * 16);
        }
#pragma unroll
    for (int bt = 0; bt < 4; bt++)
#pragma unroll
        for (int kk = 0; kk < 2; kk++) {
            int row = wn * 64 + bt * 16 + (lane & 7) + ((lane >> 4) & 1) * 8;
            boff[bt][kk] = swz(row * 64 + kk * 32 + ((lane >> 3) & 1) * 16);
        }

#pragma unroll
    for (int p = 0; p < 2; p++) {
        if (p < NC) {
            uint32_t st = sb + p * STAGE_BYTES;
#pragma unroll
            for (int j = 0; j < 8; j++)
                cpasync16(st + soff[j], gp[j] + (size_t)p * 32);
        }
        CP_COMMIT();
    }

    int stage = 0;
    for (int ch = 0; ch < NC; ch++) {
        CP_WAIT1();
        __syncthreads();

        const int pf = ch + 2;
        if (pf < NC) {
            int pstage = stage + 2; if (pstage >= NSTAGE) pstage -= NSTAGE;
            uint32_t st = sb + pstage * STAGE_BYTES;
#pragma unroll
            for (int j = 0; j < 8; j++)
                cpasync16(st + soff[j], gp[j] + (size_t)pf * 32);
        }
        CP_COMMIT();

        const uint32_t stb = sb + stage * STAGE_BYTES;
#pragma unroll
        for (int kk = 0; kk < 2; kk++) {
            uint32_t ah[2][4], al[2][4], bh4[4][4], bl4[4][4];
#pragma unroll
            for (int mt = 0; mt < 2; mt++) LDM4(ah[mt], stb + aoff[mt][kk]);
#pragma unroll
            for (int bt = 0; bt < 4; bt++) LDM4(bh4[bt], stb + 16384 + boff[bt][kk]);
#pragma unroll
            for (int mt = 0; mt < 2; mt++)
#pragma unroll
                for (int bt = 0; bt < 4; bt++) {
                    MMA16816(F.c[mt][bt * 2 + 0], ah[mt], bh4[bt][0], bh4[bt][1]);
                    MMA16816(F.c[mt][bt * 2 + 1], ah[mt], bh4[bt][2], bh4[bt][3]);
                }
#pragma unroll
            for (int bt = 0; bt < 4; bt++) LDM4(bl4[bt], stb + 24576 + boff[bt][kk]);
#pragma unroll
            for (int mt = 0; mt < 2; mt++)
#pragma unroll
                for (int bt = 0; bt < 4; bt++) {
                    MMA16816(F.c[mt][bt * 2 + 0], ah[mt], bl4[bt][0], bl4[bt][1]);
                    MMA16816(F.c[mt][bt * 2 + 1], ah[mt], bl4[bt][2], bl4[bt][3]);
                }
#pragma unroll
            for (int mt = 0; mt < 2; mt++) LDM4(al[mt], stb + 8192 + aoff[mt][kk]);
#pragma unroll
            for (int mt = 0; mt < 2; mt++)
#pragma unroll
                for (int bt = 0; bt < 4; bt++) {
                    MMA16816(F.c[mt][bt * 2 + 0], al[mt], bh4[bt][0], bh4[bt][1]);
                    MMA16816(F.c[mt][bt * 2 + 1], al[mt], bh4[bt][2], bh4[bt][3]);
                }
        }
        if (++stage == NSTAGE) stage = 0;
    }
}

// ---------------------------------------------------------------------------
// Conversion + aux kernels
// ---------------------------------------------------------------------------
__global__ void __launch_bounds__(256) split_kernel(
    const float4* __restrict__ src, __nv_bfloat162* __restrict__ dh,
    __nv_bfloat162* __restrict__ dl, int n4)
{
    int i = blockIdx.x * blockDim.x + threadIdx.x;
    if (i >= n4) return;
    float4 v = src[i];
    __nv_bfloat16 h0, h1, h2, h3, l0, l1, l2, l3;
    split2(v.x, h0, l0); split2(v.y, h1, l1);
    split2(v.z, h2, l2); split2(v.w, h3, l3);
    __nv_bfloat162 H0; H0.x = h0; H0.y = h1;
    __nv_bfloat162 H1; H1.x = h2; H1.y = h3;
    __nv_bfloat162 L0; L0.x = l0; L0.y = l1;
    __nv_bfloat162 L1; L1.x = l2; L1.y = l3;
    dh[2 * i] = H0; dh[2 * i + 1] = H1;
    dl[2 * i] = L0; dl[2 * i + 1] = L1;
}

// v[bh][j][d] fp32 -> vt hi/lo [bh][d][j] bf16
__global__ void __launch_bounds__(256) vtrans_kernel(const float* __restrict__ v)
{
    __shared__ float tile[32][33];
    const int bh = blockIdx.z;
    const int j0 = blockIdx.x * 32, d0 = blockIdx.y * 32;
    const int tx = threadIdx.x & 31, ty = threadIdx.x >> 5;
    const float* src = v + (size_t)bh * TOTL * DD;
#pragma unroll
    for (int i = 0; i < 4; i++)
        tile[ty + i * 8][tx] = src[(size_t)(j0 + ty + i * 8) * DD + d0 + tx];
    __syncthreads();
    __nv_bfloat16* dh = g_vth + (size_t)bh * DD * TOTL;
    __nv_bfloat16* dl = g_vtl + (size_t)bh * DD * TOTL;
#pragma unroll
    for (int i = 0; i < 4; i++) {
        int d = d0 + ty + i * 8, j = j0 + tx;
        float val = tile[tx][ty + i * 8];
        __nv_bfloat16 h, l; split2(val, h, l);
        dh[(size_t)d * TOTL + j] = h;
        dl[(size_t)d * TOTL + j] = l;
    }
}

// past KV -> fp32 cache rows [0,1024); K also split to g_kh/g_kl
__global__ void copy_past_kernel(const float4* __restrict__ pk,
                                 const float4* __restrict__ pv,
                                 float4* __restrict__ outk,
                                 float4* __restrict__ outv)
{
    const int n4 = BB * HH * PP * DD / 4;
    int idx = blockIdx.x * blockDim.x + threadIdx.x;
    if (idx >= 2 * n4) return;
    if (idx < n4) {
        int bh = idx >> 15, rem = idx & 32767;
        size_t d4 = (size_t)bh * (TOTL * DD / 4) + rem;
        float4 v = pk[idx];
        outk[d4] = v;
        __nv_bfloat16 h0, h1, h2, h3, l0, l1, l2, l3;
        split2(v.x, h0, l0); split2(v.y, h1, l1);
        split2(v.z, h2, l2); split2(v.w, h3, l3);
        __nv_bfloat162 H0; H0.x = h0; H0.y = h1;
        __nv_bfloat162 H1; H1.x = h2; H1.y = h3;
        __nv_bfloat162 L0; L0.x = l0; L0.y = l1;
        __nv_bfloat162 L1; L1.x = l2; L1.y = l3;
        ((__nv_bfloat162*)g_kh)[2 * d4]     = H0;
        ((__nv_bfloat162*)g_kh)[2 * d4 + 1] = H1;
        ((__nv_bfloat162*)g_kl)[2 * d4]     = L0;
        ((__nv_bfloat162*)g_kl)[2 * d4 + 1] = L1;
    } else {
        int i = idx - n4;
        int bh = i >> 15, rem = i & 32767;
        outv[(size_t)bh * (TOTL * DD / 4) + rem] = pv[i];
    }
}

// ---------------------------------------------------------------------------
// QKV projection: y = x @ W^T, z selects {Wq, Wk, Wv}
// ---------------------------------------------------------------------------
__global__ void __launch_bounds__(256) qkv_mma(float* __restrict__ outk,
                                               float* __restrict__ outv)
{
    extern __shared__ __align__(1024) char smem[];
    const int z = blockIdx.z;
    const int m0 = blockIdx.y * 128, n0 = blockIdx.x * 128;
    const __nv_bfloat16* Bh = (z == 0) ? g_wqh : (z == 1) ? g_wkh : g_wvh;
    const __nv_bfloat16* Bl = (z == 0) ? g_wql : (z == 1) ? g_wkl : g_wvl;
    Frag F;
    mma_mainloop(smem,
        g_xh + (size_t)m0 * CC, g_xl + (size_t)m0 * CC,
        Bh + (size_t)n0 * CC,   Bl + (size_t)n0 * CC, CC, CC, 64, F);

    const int lane = threadIdx.x & 31, wid = threadIdx.x >> 5;
    const int wm = wid & 3, wn = wid >> 2;
#pragma unroll
    for (int mt = 0; mt < 2; mt++)
#pragma unroll
        for (int half = 0; half < 2; half++) {
            int m = m0 + wm * 32 + mt * 16 + lane / 4 + half * 8;
            int b = m >> 10, t = m & 1023;
#pragma unroll
            for (int nt = 0; nt < 8; nt++) {
                int n = n0 + wn * 64 + nt * 8 + (lane & 3) * 2;
                int h = n >> 7, d = n & 127;
                float v0 = F.c[mt][nt][half * 2], v1 = F.c[mt][nt][half * 2 + 1];
                if (z == 0) {
                    size_t base = (((size_t)(b * 16 + h)) * 1024 + t) * 128 + d;
                    __nv_bfloat16 h0, h1, l0, l1;
                    split2(v0, h0, l0); split2(v1, h1, l1);
                    __nv_bfloat162 H; H.x = h0; H.y = h1;
                    __nv_bfloat162 L; L.x = l0; L.y = l1;
                    *(__nv_bfloat162*)(g_qh + base) = H;
                    *(__nv_bfloat162*)(g_ql + base) = L;
                } else if (z == 1) {
                    size_t base = (((size_t)(b * 16 + h)) * 2048 + 1024 + t) * 128 + d;
                    *(float2*)(outk + base) = make_float2(v0, v1);
                    __nv_bfloat16 h0, h1, l0, l1;
                    split2(v0, h0, l0); split2(v1, h1, l1);
                    __nv_bfloat162 H; H.x = h0; H.y = h1;
                    __nv_bfloat162 L; L.x = l0; L.y = l1;
                    *(__nv_bfloat162*)(g_kh + base) = H;
                    *(__nv_bfloat162*)(g_kl + base) = L;
                } else {
                    size_t base = (((size_t)(b * 16 + h)) * 2048 + 1024 + t) * 128 + d;
                    *(float2*)(outv + base) = make_float2(v0, v1);
                }
            }
        }
}

// ---------------------------------------------------------------------------
// Flash attention: scores + online softmax + PV fused.
// One CTA per (bh, 128-row q tile). 8 warps, each owns m16 x n128.
// Chunk stream per j-tile: 4 K-chunks (S phase), 4 V^T-chunks (PV phase).
// ---------------------------------------------------------------------------
__device__ __forceinline__ void fl_issue(uint32_t sb, int bh, int idx, int stg, int tid)
{
    const int jt = idx >> 3, ch = idx & 3;
    const int isV = (idx >> 2) & 1;
    const __nv_bfloat16 *sh, *sl;
    size_t ld;
    if (!isV) {
        sh = g_kh + ((size_t)bh * TOTL + jt * 128) * DD + ch * 32;
        sl = g_kl + ((size_t)bh * TOTL + jt * 128) * DD + ch * 32;
        ld = DD;
    } else {
        sh = g_vth + (size_t)bh * DD * TOTL + jt * 128 + ch * 32;
        sl = g_vtl + (size_t)bh * DD * TOTL + jt * 128 + ch * 32;
        ld = TOTL;
    }
    uint32_t st = sb + stg * FL_STAGE;
#pragma unroll
    for (int j = 0; j < 2; j++) {
        int u = tid + 256 * j, row = u >> 2, un = u & 3;
        uint32_t so = swz(row * 64 + un * 16);
        cpasync16(st + so,        sh + (size_t)row * ld + un * 8);
        cpasync16(st + 8192 + so, sl + (size_t)row * ld + un * 8);
    }
}

__global__ void __launch_bounds__(256) flash_mma()
{
    extern __shared__ __align__(1024) char smem[];
    const uint32_t sb = smem_u32(smem);
    const int bh = blockIdx.z;
    const int m0 = blockIdx.y * 128;
    const int b = bh >> 4, h = bh & 15;
    const int tid = threadIdx.x;
    const int lane = tid & 31;
    const int w = tid >> 5;
    const int r0 = lane >> 2;
    const int NJ = (1152 + m0) >> 7;    // 9..16 j-tiles
    const int NCH = NJ * 8;

    // --- load Q tile (4 k-chunks x (hi,lo)) ---
#pragma unroll
    for (int c = 0; c < 4; c++)
#pragma unroll
        for (int j = 0; j < 2; j++) {
            int u = tid + 256 * j, row = u >> 2, un = u & 3;
            uint32_t so = c * 8192 + swz(row * 64 + un * 16);
            cpasync16(sb + FL_QOFF + so,
                      g_qh + ((size_t)bh * TT + m0 + row) * DD + c * 32 + un * 8);
            cpasync16(sb + FL_QOFF + 32768 + so,
                      g_ql + ((size_t)bh * TT + m0 + row) * DD + c * 32 + un * 8);
        }
    CP_COMMIT();
    fl_issue(sb, bh, 0, 0, tid); CP_COMMIT();
    fl_issue(sb, bh, 1, 1, tid); CP_COMMIT();

    // fragment smem offsets
    uint32_t aoff[2], boff[8][2];
#pragma unroll
    for (int kk = 0; kk < 2; kk++) {
        int row = w * 16 + (lane & 15);
        aoff[kk] = swz(row * 64 + kk * 32 + ((lane >> 4) & 1) * 16);
    }
#pragma unroll
    for (int bt = 0; bt < 8; bt++)
#pragma unroll
        for (int kk = 0; kk < 2; kk++) {
            int row = bt * 16 + (lane & 7) + ((lane >> 4) & 1) * 8;
            boff[bt][kk] = swz(row * 64 + kk * 32 + ((lane >> 3) & 1) * 16);
        }

    float O[16][4];
#pragma unroll
    for (int i = 0; i < 16; i++)
#pragma unroll
        for (int k = 0; k < 4; k++) O[i][k] = 0.f;
    float ml0 = -1e30f, ml1 = -1e30f;
    float ll0 = 0.f, ll1 = 0.f;
    uint32_t ph[8][4], pl[8][4];

    int pf = 2, stage = 0;
    const float scale = 0.08838834764831845f;

    for (int jt = 0; jt < NJ; jt++) {
        float Sf[16][4];
        // ---- S phase: 4 K-chunks ----
#pragma unroll
        for (int ch = 0; ch < 4; ch++) {
            CP_WAIT1();
            __syncthreads();
            int pst = stage + 2; if (pst >= FL_NST) pst -= FL_NST;
            if (pf < NCH) fl_issue(sb, bh, pf, pst, tid);
            CP_COMMIT();
            pf++;
            const uint32_t stb = sb + stage * FL_STAGE;
            const uint32_t qb  = sb + FL_QOFF + ch * 8192;
#pragma unroll
            for (int kk = 0; kk < 2; kk++) {
                uint32_t ahf[4], alf[4], bhf[8][4], blf[8][4];
                LDM4(ahf, qb + aoff[kk]);
                LDM4(alf, qb + 32768 + aoff[kk]);
#pragma unroll
                for (int bt = 0; bt < 8; bt++) {
                    LDM4(bhf[bt], stb + boff[bt][kk]);
                    LDM4(blf[bt], stb + 8192 + boff[bt][kk]);
                }
                if (ch == 0 && kk == 0) {
#pragma unroll
                    for (int i = 0; i < 16; i++)
#pragma unroll
                        for (int k = 0; k < 4; k++) Sf[i][k] = 0.f;
                }
#pragma unroll
                for (int bt = 0; bt < 8; bt++) {
                    MMA16816(Sf[bt * 2 + 0], ahf, bhf[bt][0], bhf[bt][1]);
                    MMA16816(Sf[bt * 2 + 1], ahf, bhf[bt][2], bhf[bt][3]);
                    MMA16816(Sf[bt * 2 + 0], ahf, blf[bt][0], blf[bt][1]);
                    MMA16816(Sf[bt * 2 + 1], ahf, blf[bt][2], blf[bt][3]);
                    MMA16816(Sf[bt * 2 + 0], alf, bhf[bt][0], bhf[bt][1]);
                    MMA16816(Sf[bt * 2 + 1], alf, bhf[bt][2], bhf[bt][3]);
                }
            }
            if (++stage == FL_NST) stage = 0;
        }

        // ---- online softmax on fragments ----
#pragma unroll
        for (int nt = 0; nt < 16; nt++)
#pragma unroll
            for (int ci = 0; ci < 4; ci++) Sf[nt][ci] *= scale;
        if (jt == NJ - 1) {
            // triangular tile: local col jj valid iff jj <= local row
#pragma unroll
            for (int nt = 0; nt < 16; nt++)
#pragma unroll
                for (int ci = 0; ci < 4; ci++) {
                    int jj = nt * 8 + (lane & 3) * 2 + (ci & 1);
                    int tl = w * 16 + r0 + ((ci >> 1) << 3);
                    if (jj > tl) Sf[nt][ci] = -1e30f;
                }
        }
        float mc0 = -1e30f, mc1 = -1e30f;
#pragma unroll
        for (int nt = 0; nt < 16; nt++) {
            mc0 = fmaxf(mc0, fmaxf(Sf[nt][0], Sf[nt][1]));
            mc1 = fmaxf(mc1, fmaxf(Sf[nt][2], Sf[nt][3]));
        }
        mc0 = fmaxf(mc0, __shfl_xor_sync(0xffffffffu, mc0, 1));
        mc0 = fmaxf(mc0, __shfl_xor_sync(0xffffffffu, mc0, 2));
        mc1 = fmaxf(mc1, __shfl_xor_sync(0xffffffffu, mc1, 1));
        mc1 = fmaxf(mc1, __shfl_xor_sync(0xffffffffu, mc1, 2));
        float mn0 = fmaxf(ml0, mc0), mn1 = fmaxf(ml1, mc1);
        float a0 = __expf(ml0 - mn0), a1 = __expf(ml1 - mn1);
        ml0 = mn0; ml1 = mn1;
        ll0 *= a0; ll1 *= a1;
#pragma unroll
        for (int nt = 0; nt < 16; nt++) {
            O[nt][0] *= a0; O[nt][1] *= a0;
            O[nt][2] *= a1; O[nt][3] *= a1;
        }
#pragma unroll
        for (int nt = 0; nt < 16; nt++) {
            float p0 = __expf(Sf[nt][0] - mn0), p1 = __expf(Sf[nt][1] - mn0);
            float p2 = __expf(Sf[nt][2] - mn1), p3 = __expf(Sf[nt][3] - mn1);
            ll0 += p0 + p1; ll1 += p2 + p3;
            __nv_bfloat16 h0, h1, h2, h3, l0, l1, l2, l3;
            split2(p0, h0, l0); split2(p1, h1, l1);
            split2(p2, h2, l2); split2(p3, h3, l3);
            int kkj = nt >> 1, half = nt & 1;
            ph[kkj][half * 2 + 0] = packbf(h0, h1);
            ph[kkj][half * 2 + 1] = packbf(h2, h3);
            pl[kkj][half * 2 + 0] = packbf(l0, l1);
            pl[kkj][half * 2 + 1] = packbf(l2, l3);
        }

        // ---- PV phase: 4 V^T-chunks ----
#pragma unroll
        for (int ch = 0; ch < 4; ch++) {
            CP_WAIT1();
            __syncthreads();
            int pst = stage + 2; if (pst >= FL_NST) pst -= FL_NST;
            if (pf < NCH) fl_issue(sb, bh, pf, pst, tid);
            CP_COMMIT();
            pf++;
            const uint32_t stb = sb + stage * FL_STAGE;
#pragma unroll
            for (int kk = 0; kk < 2; kk++) {
                const int kkj = ch * 2 + kk;
                uint32_t vhf[8][4], vlf[8][4];
#pragma unroll
                for (int dt = 0; dt < 8; dt++) {
                    LDM4(vhf[dt], stb + boff[dt][kk]);
                    LDM4(vlf[dt], stb + 8192 + boff[dt][kk]);
                }
#pragma unroll
                for (int dt = 0; dt < 8; dt++) {
                    MMA16816(O[dt * 2 + 0], ph[kkj], vhf[dt][0], vhf[dt][1]);
                    MMA16816(O[dt * 2 + 1], ph[kkj], vhf[dt][2], vhf[dt][3]);
                    MMA16816(O[dt * 2 + 0], ph[kkj], vlf[dt][0], vlf[dt][1]);
                    MMA16816(O[dt * 2 + 1], ph[kkj], vlf[dt][2], vlf[dt][3]);
                    MMA16816(O[dt * 2 + 0], pl[kkj], vhf[dt][0], vhf[dt][1]);
                    MMA16816(O[dt * 2 + 1], pl[kkj], vhf[dt][2], vhf[dt][3]);
                }
            }
            if (++stage == FL_NST) stage = 0;
        }
    }

    // ---- epilogue: normalize, split, write [B,T,C] ----
    ll0 += __shfl_xor_sync(0xffffffffu, ll0, 1);
    ll0 += __shfl_xor_sync(0xffffffffu, ll0, 2);
    ll1 += __shfl_xor_sync(0xffffffffu, ll1, 1);
    ll1 += __shfl_xor_sync(0xffffffffu, ll1, 2);
    const float inv0 = 1.f / ll0, inv1 = 1.f / ll1;
    const int t0 = m0 + w * 16 + r0, t1 = t0 + 8;
#pragma unroll
    for (int nt = 0; nt < 16; nt++) {
        int d = nt * 8 + (lane & 3) * 2;
        float v0 = O[nt][0] * inv0, v1 = O[nt][1] * inv0;
        float v2 = O[nt][2] * inv1, v3 = O[nt][3] * inv1;
        size_t b0 = ((size_t)(b * 1024 + t0)) * 2048 + h * 128 + d;
        size_t b1 = ((size_t)(b * 1024 + t1)) * 2048 + h * 128 + d;
        __nv_bfloat16 h0, h1, h2, h3, l0, l1, l2, l3;
        split2(v0, h0, l0); split2(v1, h1, l1);
        split2(v2, h2, l2); split2(v3, h3, l3);
        __nv_bfloat162 H0; H0.x = h0; H0.y = h1;
        __nv_bfloat162 L0; L0.x = l0; L0.y = l1;
        __nv_bfloat162 H1; H1.x = h2; H1.y = h3;
        __nv_bfloat162 L1; L1.x = l2; L1.y = l3;
        *(__nv_bfloat162*)(g_aoh + b0) = H0;
        *(__nv_bfloat162*)(g_aol + b0) = L0;
        *(__nv_bfloat162*)(g_aoh + b1) = H1;
        *(__nv_bfloat162*)(g_aol + b1) = L1;
    }
}

// ---------------------------------------------------------------------------
// Output projection: out = ao @ Wp^T + bp
// ---------------------------------------------------------------------------
__global__ void __launch_bounds__(256) proj_mma(const float* __restrict__ bp,
                                                float* __restrict__ out)
{
    extern __shared__ __align__(1024) char smem[];
    const int m0 = blockIdx.y * 128, n0 = blockIdx.x * 128;
    Frag F;
    mma_mainloop(smem,
        g_aoh + (size_t)m0 * CC, g_aol + (size_t)m0 * CC,
        g_wph + (size_t)n0 * CC, g_wpl + (size_t)n0 * CC, CC, CC, 64, F);

    const int lane = threadIdx.x & 31, wid = threadIdx.x >> 5;
    const int wm = wid & 3, wn = wid >> 2;
#pragma unroll
    for (int mt = 0; mt < 2; mt++)
#pragma unroll
        for (int half = 0; half < 2; half++) {
            int m = m0 + wm * 32 + mt * 16 + lane / 4 + half * 8;
#pragma unroll
            for (int nt = 0; nt < 8; nt++) {
                int n = n0 + wn * 64 + nt * 8 + (lane & 3) * 2;
                float2 bias = *(const float2*)(bp + n);
                *(float2*)(out + (size_t)m * 2048 + n) =
                    make_float2(F.c[mt][nt][half * 2] + bias.x,
                                F.c[mt][nt][half * 2 + 1] + bias.y);
            }
        }
}

// ---------------------------------------------------------------------------
extern "C" void kernel_launch(void* const* d_in, const int* in_sizes, int n_in,
                              void* d_out, int out_size)
{
    (void)in_sizes; (void)n_in; (void)out_size;
    const float* x      = (const float*)d_in[0];
    const float* past_k = (const float*)d_in[1];
    const float* past_v = (const float*)d_in[2];
    const float* Wk     = (const float*)d_in[3];
    const float* Wq     = (const float*)d_in[4];
    const float* Wv     = (const float*)d_in[5];
    const float* Wp     = (const float*)d_in[6];
    const float* bp     = (const float*)d_in[7];

    float* out  = (float*)d_out;
    float* outk = out + (size_t)BB * TT * CC;
    float* outv = outk + (size_t)BHN * TOTL * DD;

    cudaFuncSetAttribute(qkv_mma,   cudaFuncAttributeMaxDynamicSharedMemorySize, DSMEM);
    cudaFuncSetAttribute(proj_mma,  cudaFuncAttributeMaxDynamicSharedMemorySize, DSMEM);
    cudaFuncSetAttribute(flash_mma, cudaFuncAttributeMaxDynamicSharedMemorySize, FL_DSMEM);

    __nv_bfloat16 *xh, *xl, *wqh, *wql, *wkh, *wkl, *wvh, *wvl, *wph, *wpl;
    cudaGetSymbolAddress((void**)&xh,  g_xh);  cudaGetSymbolAddress((void**)&xl,  g_xl);
    cudaGetSymbolAddress((void**)&wqh, g_wqh); cudaGetSymbolAddress((void**)&wql, g_wql);
    cudaGetSymbolAddress((void**)&wkh, g_wkh); cudaGetSymbolAddress((void**)&wkl, g_wkl);
    cudaGetSymbolAddress((void**)&wvh, g_wvh); cudaGetSymbolAddress((void**)&wvl, g_wvl);
    cudaGetSymbolAddress((void**)&wph, g_wph); cudaGetSymbolAddress((void**)&wpl, g_wpl);

    const int n4w = CC * CC / 4;
    const int nb  = (n4w + 255) / 256;

    // 1. split fp32 inputs into bf16 hi/lo
    split_kernel<<<nb, 256>>>((const float4*)x,  (__nv_bfloat162*)xh,  (__nv_bfloat162*)xl,  n4w);
    split_kernel<<<nb, 256>>>((const float4*)Wq, (__nv_bfloat162*)wqh, (__nv_bfloat162*)wql, n4w);
    split_kernel<<<nb, 256>>>((const float4*)Wk, (__nv_bfloat162*)wkh, (__nv_bfloat162*)wkl, n4w);
    split_kernel<<<nb, 256>>>((const float4*)Wv, (__nv_bfloat162*)wvh, (__nv_bfloat162*)wvl, n4w);
    split_kernel<<<nb, 256>>>((const float4*)Wp, (__nv_bfloat162*)wph, (__nv_bfloat162*)wpl, n4w);

    // 2. past KV -> fp32 cache (K also split to bf16 hi/lo)
    copy_past_kernel<<<8192, 256>>>((const float4*)past_k, (const float4*)past_v,
                                    (float4*)outk, (float4*)outv);

    // 3. QKV projection
    qkv_mma<<<dim3(16, 16, 3), 256, DSMEM>>>(outk, outv);

    // 4. transpose+split V cache
    vtrans_kernel<<<dim3(64, 4, 32), 256>>>(outv);

    // 5-7. fused flash attention (scores + softmax + PV)
    flash_mma<<<dim3(1, 8, 32), 256, FL_DSMEM>>>();

    // 8. output projection + bias
    proj_mma<<<dim3(16, 16), 256, DSMEM>>>(bp, out);
}

// round 8
// speedup vs baseline: 4.6601x; 1.0311x over previous
#include <cuda_runtime.h>
#include <cuda_bf16.h>
#include <math.h>
#include <stdint.h>

// Problem constants
#define BB   2
#define TT   1024
#define CC   2048
#define HH   16
#define DD   128
#define PP   1024
#define TOTL 2048
#define BHN  32

#define STAGE_BYTES 32768
#define NSTAGE      4
#define DSMEM       (NSTAGE * STAGE_BYTES)   // 128 KB (qkv/proj GEMMs)

// flash kernel smem
#define FL_STAGE  16384
#define FL_NST    4
#define FL_QOFF   (FL_NST * FL_STAGE)        // 65536
#define FL_DSMEM  (FL_QOFF + 65536)          // 131072

// ---------------------------------------------------------------------------
// Device scratch (allocation-free)
// ---------------------------------------------------------------------------
__device__ __nv_bfloat16 g_xh [(size_t)CC * CC], g_xl [(size_t)CC * CC];
__device__ __nv_bfloat16 g_wqh[(size_t)CC * CC], g_wql[(size_t)CC * CC];
__device__ __nv_bfloat16 g_wkh[(size_t)CC * CC], g_wkl[(size_t)CC * CC];
__device__ __nv_bfloat16 g_wvh[(size_t)CC * CC], g_wvl[(size_t)CC * CC];
__device__ __nv_bfloat16 g_wph[(size_t)CC * CC], g_wpl[(size_t)CC * CC];
__device__ __nv_bfloat16 g_qh [(size_t)BHN * TT * DD],   g_ql [(size_t)BHN * TT * DD];
__device__ __nv_bfloat16 g_kh [(size_t)BHN * TOTL * DD], g_kl [(size_t)BHN * TOTL * DD];
__device__ __nv_bfloat16 g_vth[(size_t)BHN * DD * TOTL], g_vtl[(size_t)BHN * DD * TOTL];
__device__ __nv_bfloat16 g_aoh[(size_t)BB * TT * CC],    g_aol[(size_t)BB * TT * CC];

__device__ __forceinline__ uint32_t smem_u32(const void* p) {
    uint32_t a;
    asm("{ .reg .u64 t; cvta.to.shared.u64 t, %1; cvt.u32.u64 %0, t; }" : "=r"(a) : "l"(p));
    return a;
}
__device__ __forceinline__ void split2(float v, __nv_bfloat16& h, __nv_bfloat16& l) {
    h = __float2bfloat16(v);
    l = __float2bfloat16(v - __bfloat162float(h));
}
__device__ __forceinline__ uint32_t packbf(__nv_bfloat16 a, __nv_bfloat16 b) {
    __nv_bfloat162 t; t.x = a; t.y = b;
    return *(uint32_t*)&t;
}
__device__ __forceinline__ void cpasync16(uint32_t dst, const void* src) {
    asm volatile("cp.async.cg.shared.global [%0], [%1], 16;" :: "r"(dst), "l"(src));
}
#define CP_COMMIT() asm volatile("cp.async.commit_group;" ::: "memory")
#define CP_WAIT2()  asm volatile("cp.async.wait_group 2;"  ::: "memory")

#define LDM4(r, addr)                                                        \
    asm volatile("ldmatrix.sync.aligned.m8n8.x4.shared.b16 {%0,%1,%2,%3}, [%4];" \
        : "=r"((r)[0]), "=r"((r)[1]), "=r"((r)[2]), "=r"((r)[3]) : "r"(addr))

#define MMA16816(c, a, b0v, b1v)                                             \
    asm volatile("mma.sync.aligned.m16n8k16.row.col.f32.bf16.bf16.f32 "      \
        "{%0,%1,%2,%3}, {%4,%5,%6,%7}, {%8,%9}, {%0,%1,%2,%3};"              \
        : "+f"((c)[0]), "+f"((c)[1]), "+f"((c)[2]), "+f"((c)[3])             \
        : "r"((a)[0]), "r"((a)[1]), "r"((a)[2]), "r"((a)[3]),                \
          "r"(b0v), "r"(b1v))

__device__ __forceinline__ uint32_t swz(uint32_t o) { return o ^ ((o >> 3) & 0x30); }

// ---------------------------------------------------------------------------
// Dense GEMM mainloop: 4-stage cp.async ring (prefetch distance 3),
// 8 warps 4x2, CTA 128x128, K-chunk 32, C = AhBh + AlBh + AhBl.
// Term groups separated to avoid accumulator RAW stalls.
// ---------------------------------------------------------------------------
struct Frag { float c[2][8][4]; };

__device__ __forceinline__ void mma_mainloop(
    char* smem,
    const __nv_bfloat16* __restrict__ Ah, const __nv_bfloat16* __restrict__ Al,
    const __nv_bfloat16* __restrict__ Bh, const __nv_bfloat16* __restrict__ Bl,
    size_t ldA, size_t ldB, int NC, Frag& F)
{
    const uint32_t sb = smem_u32(smem);
    const int tid  = threadIdx.x;
    const int lane = tid & 31;
    const int wid  = tid >> 5;
    const int wm   = wid & 3;
    const int wn   = wid >> 2;

#pragma unroll
    for (int i = 0; i < 2; i++)
#pragma unroll
        for (int j = 0; j < 8; j++)
#pragma unroll
            for (int k = 0; k < 4; k++) F.c[i][j][k] = 0.f;

    const __nv_bfloat16* gp[8];
    uint32_t soff[8];
#pragma unroll
    for (int j = 0; j < 8; j++) {
        int u = tid + 256 * (j & 1);
        int row = u >> 2, un = u & 3, T = j >> 1;
        const __nv_bfloat16* base = (T == 0) ? Ah : (T == 1) ? Al : (T == 2) ? Bh : Bl;
        size_t ld = (T < 2) ? ldA : ldB;
        gp[j]   = base + (size_t)row * ld + un * 8;
        soff[j] = T * 8192 + swz(row * 64 + un * 16);
    }

    uint32_t aoff[2][2], boff[4][2];
#pragma unroll
    for (int mt = 0; mt < 2; mt++)
#pragma unroll
        for (int kk = 0; kk < 2; kk++) {
            int row = wm * 32 + mt * 16 + (lane & 15);
            aoff[mt][kk] = swz(row * 64 + kk * 32 + ((lane >> 4) & 1) * 16);
        }
#pragma unroll
    for (int bt = 0; bt < 4; bt++)
#pragma unroll
        for (int kk = 0; kk < 2; kk++) {
            int row = wn * 64 + bt * 16 + (lane & 7) + ((lane >> 4) & 1) * 8;
            boff[bt][kk] = swz(row * 64 + kk * 32 + ((lane >> 3) & 1) * 16);
        }

#pragma unroll
    for (int p = 0; p < 3; p++) {
        if (p < NC) {
            uint32_t st = sb + p * STAGE_BYTES;
#pragma unroll
            for (int j = 0; j < 8; j++)
                cpasync16(st + soff[j], gp[j] + (size_t)p * 32);
        }
        CP_COMMIT();
    }

    int stage = 0;
    for (int ch = 0; ch < NC; ch++) {
        CP_WAIT2();
        __syncthreads();

        const int pf = ch + 3;
        if (pf < NC) {
            int pstage = stage + 3; if (pstage >= NSTAGE) pstage -= NSTAGE;
            uint32_t st = sb + pstage * STAGE_BYTES;
#pragma unroll
            for (int j = 0; j < 8; j++)
                cpasync16(st + soff[j], gp[j] + (size_t)pf * 32);
        }
        CP_COMMIT();

        const uint32_t stb = sb + stage * STAGE_BYTES;
#pragma unroll
        for (int kk = 0; kk < 2; kk++) {
            uint32_t ah[2][4], al[2][4], bf4[4][4];
#pragma unroll
            for (int mt = 0; mt < 2; mt++) LDM4(ah[mt], stb + aoff[mt][kk]);
#pragma unroll
            for (int mt = 0; mt < 2; mt++) LDM4(al[mt], stb + 8192 + aoff[mt][kk]);
            // Bh: term1 (ah x bh), term3 (al x bh)
#pragma unroll
            for (int bt = 0; bt < 4; bt++) LDM4(bf4[bt], stb + 16384 + boff[bt][kk]);
#pragma unroll
            for (int mt = 0; mt < 2; mt++)
#pragma unroll
                for (int bt = 0; bt < 4; bt++) {
                    MMA16816(F.c[mt][bt * 2 + 0], ah[mt], bf4[bt][0], bf4[bt][1]);
                    MMA16816(F.c[mt][bt * 2 + 1], ah[mt], bf4[bt][2], bf4[bt][3]);
                }
#pragma unroll
            for (int mt = 0; mt < 2; mt++)
#pragma unroll
                for (int bt = 0; bt < 4; bt++) {
                    MMA16816(F.c[mt][bt * 2 + 0], al[mt], bf4[bt][0], bf4[bt][1]);
                    MMA16816(F.c[mt][bt * 2 + 1], al[mt], bf4[bt][2], bf4[bt][3]);
                }
            // Bl: term2 (ah x bl)
#pragma unroll
            for (int bt = 0; bt < 4; bt++) LDM4(bf4[bt], stb + 24576 + boff[bt][kk]);
#pragma unroll
            for (int mt = 0; mt < 2; mt++)
#pragma unroll
                for (int bt = 0; bt < 4; bt++) {
                    MMA16816(F.c[mt][bt * 2 + 0], ah[mt], bf4[bt][0], bf4[bt][1]);
                    MMA16816(F.c[mt][bt * 2 + 1], ah[mt], bf4[bt][2], bf4[bt][3]);
                }
        }
        if (++stage == NSTAGE) stage = 0;
    }
}

// ---------------------------------------------------------------------------
// Fused prep: tasks 0-4 split {x,Wq,Wk,Wv,Wp}; 5 = past_k copy+split; 6 = past_v copy
// ---------------------------------------------------------------------------
__global__ void __launch_bounds__(256) prep_kernel(
    const float4* __restrict__ x,  const float4* __restrict__ Wq,
    const float4* __restrict__ Wk, const float4* __restrict__ Wv,
    const float4* __restrict__ Wp, const float4* __restrict__ pk,
    const float4* __restrict__ pv, float4* __restrict__ outk,
    float4* __restrict__ outv)
{
    const int task = blockIdx.y;
    const int i = blockIdx.x * blockDim.x + threadIdx.x;   // < 1048576

    if (task == 6) {
        int bh = i >> 15, rem = i & 32767;
        outv[(size_t)bh * (TOTL * DD / 4) + rem] = pv[i];
        return;
    }

    float4 v;
    __nv_bfloat162 *dh, *dl;
    size_t o2;
    if (task == 5) {
        int bh = i >> 15, rem = i & 32767;
        size_t d4 = (size_t)bh * (TOTL * DD / 4) + rem;
        v = pk[i];
        outk[d4] = v;
        dh = (__nv_bfloat162*)g_kh; dl = (__nv_bfloat162*)g_kl;
        o2 = 2 * d4;
    } else {
        const float4* s = (task == 0) ? x : (task == 1) ? Wq :
                          (task == 2) ? Wk : (task == 3) ? Wv : Wp;
        v = s[i];
        dh = (__nv_bfloat162*)((task == 0) ? g_xh : (task == 1) ? g_wqh :
                               (task == 2) ? g_wkh : (task == 3) ? g_wvh : g_wph);
        dl = (__nv_bfloat162*)((task == 0) ? g_xl : (task == 1) ? g_wql :
                               (task == 2) ? g_wkl : (task == 3) ? g_wvl : g_wpl);
        o2 = 2 * (size_t)i;
    }
    __nv_bfloat16 h0, h1, h2, h3, l0, l1, l2, l3;
    split2(v.x, h0, l0); split2(v.y, h1, l1);
    split2(v.z, h2, l2); split2(v.w, h3, l3);
    __nv_bfloat162 H0; H0.x = h0; H0.y = h1;
    __nv_bfloat162 H1; H1.x = h2; H1.y = h3;
    __nv_bfloat162 L0; L0.x = l0; L0.y = l1;
    __nv_bfloat162 L1; L1.x = l2; L1.y = l3;
    dh[o2] = H0; dh[o2 + 1] = H1;
    dl[o2] = L0; dl[o2 + 1] = L1;
}

// v[bh][j][d] fp32 -> vt hi/lo [bh][d][j] bf16
__global__ void __launch_bounds__(256) vtrans_kernel(const float* __restrict__ v)
{
    __shared__ float tile[32][33];
    const int bh = blockIdx.z;
    const int j0 = blockIdx.x * 32, d0 = blockIdx.y * 32;
    const int tx = threadIdx.x & 31, ty = threadIdx.x >> 5;
    const float* src = v + (size_t)bh * TOTL * DD;
#pragma unroll
    for (int i = 0; i < 4; i++)
        tile[ty + i * 8][tx] = src[(size_t)(j0 + ty + i * 8) * DD + d0 + tx];
    __syncthreads();
    __nv_bfloat16* dh = g_vth + (size_t)bh * DD * TOTL;
    __nv_bfloat16* dl = g_vtl + (size_t)bh * DD * TOTL;
#pragma unroll
    for (int i = 0; i < 4; i++) {
        int d = d0 + ty + i * 8, j = j0 + tx;
        float val = tile[tx][ty + i * 8];
        __nv_bfloat16 h, l; split2(val, h, l);
        dh[(size_t)d * TOTL + j] = h;
        dl[(size_t)d * TOTL + j] = l;
    }
}

// ---------------------------------------------------------------------------
// QKV projection: y = x @ W^T, z selects {Wq, Wk, Wv}
// ---------------------------------------------------------------------------
__global__ void __launch_bounds__(256) qkv_mma(float* __restrict__ outk,
                                               float* __restrict__ outv)
{
    extern __shared__ __align__(1024) char smem[];
    const int z = blockIdx.z;
    const int m0 = blockIdx.y * 128, n0 = blockIdx.x * 128;
    const __nv_bfloat16* Bh = (z == 0) ? g_wqh : (z == 1) ? g_wkh : g_wvh;
    const __nv_bfloat16* Bl = (z == 0) ? g_wql : (z == 1) ? g_wkl : g_wvl;
    Frag F;
    mma_mainloop(smem,
        g_xh + (size_t)m0 * CC, g_xl + (size_t)m0 * CC,
        Bh + (size_t)n0 * CC,   Bl + (size_t)n0 * CC, CC, CC, 64, F);

    const int lane = threadIdx.x & 31, wid = threadIdx.x >> 5;
    const int wm = wid & 3, wn = wid >> 2;
#pragma unroll
    for (int mt = 0; mt < 2; mt++)
#pragma unroll
        for (int half = 0; half < 2; half++) {
            int m = m0 + wm * 32 + mt * 16 + lane / 4 + half * 8;
            int b = m >> 10, t = m & 1023;
#pragma unroll
            for (int nt = 0; nt < 8; nt++) {
                int n = n0 + wn * 64 + nt * 8 + (lane & 3) * 2;
                int h = n >> 7, d = n & 127;
                float v0 = F.c[mt][nt][half * 2], v1 = F.c[mt][nt][half * 2 + 1];
                if (z == 0) {
                    size_t base = (((size_t)(b * 16 + h)) * 1024 + t) * 128 + d;
                    __nv_bfloat16 h0, h1, l0, l1;
                    split2(v0, h0, l0); split2(v1, h1, l1);
                    __nv_bfloat162 H; H.x = h0; H.y = h1;
                    __nv_bfloat162 L; L.x = l0; L.y = l1;
                    *(__nv_bfloat162*)(g_qh + base) = H;
                    *(__nv_bfloat162*)(g_ql + base) = L;
                } else if (z == 1) {
                    size_t base = (((size_t)(b * 16 + h)) * 2048 + 1024 + t) * 128 + d;
                    *(float2*)(outk + base) = make_float2(v0, v1);
                    __nv_bfloat16 h0, h1, l0, l1;
                    split2(v0, h0, l0); split2(v1, h1, l1);
                    __nv_bfloat162 H; H.x = h0; H.y = h1;
                    __nv_bfloat162 L; L.x = l0; L.y = l1;
                    *(__nv_bfloat162*)(g_kh + base) = H;
                    *(__nv_bfloat162*)(g_kl + base) = L;
                } else {
                    size_t base = (((size_t)(b * 16 + h)) * 2048 + 1024 + t) * 128 + d;
                    *(float2*)(outv + base) = make_float2(v0, v1);
                }
            }
        }
}

// ---------------------------------------------------------------------------
// Flash attention: scores + online softmax + PV fused.
// One CTA per (bh, 128-row q tile); 8 warps each own m16 x n128.
// ---------------------------------------------------------------------------
__device__ __forceinline__ void fl_issue(uint32_t sb, int bh, int idx, int stg, int tid)
{
    const int jt = idx >> 3, ch = idx & 3;
    const int isV = (idx >> 2) & 1;
    const __nv_bfloat16 *sh, *sl;
    size_t ld;
    if (!isV) {
        sh = g_kh + ((size_t)bh * TOTL + jt * 128) * DD + ch * 32;
        sl = g_kl + ((size_t)bh * TOTL + jt * 128) * DD + ch * 32;
        ld = DD;
    } else {
        sh = g_vth + (size_t)bh * DD * TOTL + jt * 128 + ch * 32;
        sl = g_vtl + (size_t)bh * DD * TOTL + jt * 128 + ch * 32;
        ld = TOTL;
    }
    uint32_t st = sb + stg * FL_STAGE;
#pragma unroll
    for (int j = 0; j < 2; j++) {
        int u = tid + 256 * j, row = u >> 2, un = u & 3;
        uint32_t so = swz(row * 64 + un * 16);
        cpasync16(st + so,        sh + (size_t)row * ld + un * 8);
        cpasync16(st + 8192 + so, sl + (size_t)row * ld + un * 8);
    }
}

__global__ void __launch_bounds__(256) flash_mma()
{
    extern __shared__ __align__(1024) char smem[];
    const uint32_t sb = smem_u32(smem);
    const int bh = blockIdx.z;
    const int m0 = blockIdx.y * 128;
    const int b = bh >> 4, h = bh & 15;
    const int tid = threadIdx.x;
    const int lane = tid & 31;
    const int w = tid >> 5;
    const int r0 = lane >> 2;
    const int NJ = (1152 + m0) >> 7;
    const int NCH = NJ * 8;

    // Q tile (4 k-chunks x (hi,lo))
#pragma unroll
    for (int c = 0; c < 4; c++)
#pragma unroll
        for (int j = 0; j < 2; j++) {
            int u = tid + 256 * j, row = u >> 2, un = u & 3;
            uint32_t so = c * 8192 + swz(row * 64 + un * 16);
            cpasync16(sb + FL_QOFF + so,
                      g_qh + ((size_t)bh * TT + m0 + row) * DD + c * 32 + un * 8);
            cpasync16(sb + FL_QOFF + 32768 + so,
                      g_ql + ((size_t)bh * TT + m0 + row) * DD + c * 32 + un * 8);
        }
    CP_COMMIT();
    fl_issue(sb, bh, 0, 0, tid); CP_COMMIT();
    fl_issue(sb, bh, 1, 1, tid); CP_COMMIT();
    fl_issue(sb, bh, 2, 2, tid); CP_COMMIT();

    uint32_t aoff[2], boff[8][2];
#pragma unroll
    for (int kk = 0; kk < 2; kk++) {
        int row = w * 16 + (lane & 15);
        aoff[kk] = swz(row * 64 + kk * 32 + ((lane >> 4) & 1) * 16);
    }
#pragma unroll
    for (int bt = 0; bt < 8; bt++)
#pragma unroll
        for (int kk = 0; kk < 2; kk++) {
            int row = bt * 16 + (lane & 7) + ((lane >> 4) & 1) * 8;
            boff[bt][kk] = swz(row * 64 + kk * 32 + ((lane >> 3) & 1) * 16);
        }

    float O[16][4];
#pragma unroll
    for (int i = 0; i < 16; i++)
#pragma unroll
        for (int k = 0; k < 4; k++) O[i][k] = 0.f;
    float ml0 = -1e30f, ml1 = -1e30f;
    float ll0 = 0.f, ll1 = 0.f;
    uint32_t ph[8][4], pl[8][4];

    int pf = 3, stage = 0;
    const float scale = 0.08838834764831845f;

    for (int jt = 0; jt < NJ; jt++) {
        float Sf[16][4];
        // ---- S phase: 4 K-chunks ----
#pragma unroll
        for (int ch = 0; ch < 4; ch++) {
            CP_WAIT2();
            __syncthreads();
            int pst = stage + 3; if (pst >= FL_NST) pst -= FL_NST;
            if (pf < NCH) fl_issue(sb, bh, pf, pst, tid);
            CP_COMMIT();
            pf++;
            const uint32_t stb = sb + stage * FL_STAGE;
            const uint32_t qb  = sb + FL_QOFF + ch * 8192;
            if (ch == 0) {
#pragma unroll
                for (int i = 0; i < 16; i++)
#pragma unroll
                    for (int k = 0; k < 4; k++) Sf[i][k] = 0.f;
            }
#pragma unroll
            for (int kk = 0; kk < 2; kk++) {
                uint32_t ahf[4], alf[4], bf[8][4];
                LDM4(ahf, qb + aoff[kk]);
                LDM4(alf, qb + 32768 + aoff[kk]);
#pragma unroll
                for (int bt = 0; bt < 8; bt++) LDM4(bf[bt], stb + boff[bt][kk]);
#pragma unroll
                for (int bt = 0; bt < 8; bt++) {
                    MMA16816(Sf[bt * 2 + 0], ahf, bf[bt][0], bf[bt][1]);
                    MMA16816(Sf[bt * 2 + 1], ahf, bf[bt][2], bf[bt][3]);
                }
#pragma unroll
                for (int bt = 0; bt < 8; bt++) {
                    MMA16816(Sf[bt * 2 + 0], alf, bf[bt][0], bf[bt][1]);
                    MMA16816(Sf[bt * 2 + 1], alf, bf[bt][2], bf[bt][3]);
                }
#pragma unroll
                for (int bt = 0; bt < 8; bt++) LDM4(bf[bt], stb + 8192 + boff[bt][kk]);
#pragma unroll
                for (int bt = 0; bt < 8; bt++) {
                    MMA16816(Sf[bt * 2 + 0], ahf, bf[bt][0], bf[bt][1]);
                    MMA16816(Sf[bt * 2 + 1], ahf, bf[bt][2], bf[bt][3]);
                }
            }
            if (++stage == FL_NST) stage = 0;
        }

        // ---- online softmax ----
#pragma unroll
        for (int nt = 0; nt < 16; nt++)
#pragma unroll
            for (int ci = 0; ci < 4; ci++) Sf[nt][ci] *= scale;
        if (jt == NJ - 1) {
#pragma unroll
            for (int nt = 0; nt < 16; nt++)
#pragma unroll
                for (int ci = 0; ci < 4; ci++) {
                    int jj = nt * 8 + (lane & 3) * 2 + (ci & 1);
                    int tl = w * 16 + r0 + ((ci >> 1) << 3);
                    if (jj > tl) Sf[nt][ci] = -1e30f;
                }
        }
        float mc0 = -1e30f, mc1 = -1e30f;
#pragma unroll
        for (int nt = 0; nt < 16; nt++) {
            mc0 = fmaxf(mc0, fmaxf(Sf[nt][0], Sf[nt][1]));
            mc1 = fmaxf(mc1, fmaxf(Sf[nt][2], Sf[nt][3]));
        }
        mc0 = fmaxf(mc0, __shfl_xor_sync(0xffffffffu, mc0, 1));
        mc0 = fmaxf(mc0, __shfl_xor_sync(0xffffffffu, mc0, 2));
        mc1 = fmaxf(mc1, __shfl_xor_sync(0xffffffffu, mc1, 1));
        mc1 = fmaxf(mc1, __shfl_xor_sync(0xffffffffu, mc1, 2));
        float mn0 = fmaxf(ml0, mc0), mn1 = fmaxf(ml1, mc1);
        float a0 = __expf(ml0 - mn0), a1 = __expf(ml1 - mn1);
        ml0 = mn0; ml1 = mn1;
        ll0 *= a0; ll1 *= a1;
#pragma unroll
        for (int nt = 0; nt < 16; nt++) {
            O[nt][0] *= a0; O[nt][1] *= a0;
            O[nt][2] *= a1; O[nt][3] *= a1;
        }
#pragma unroll
        for (int nt = 0; nt < 16; nt++) {
            float p0 = __expf(Sf[nt][0] - mn0), p1 = __expf(Sf[nt][1] - mn0);
            float p2 = __expf(Sf[nt][2] - mn1), p3 = __expf(Sf[nt][3] - mn1);
            ll0 += p0 + p1; ll1 += p2 + p3;
            __nv_bfloat16 h0, h1, h2, h3, l0, l1, l2, l3;
            split2(p0, h0, l0); split2(p1, h1, l1);
            split2(p2, h2, l2); split2(p3, h3, l3);
            int kkj = nt >> 1, half = nt & 1;
            ph[kkj][half * 2 + 0] = packbf(h0, h1);
            ph[kkj][half * 2 + 1] = packbf(h2, h3);
            pl[kkj][half * 2 + 0] = packbf(l0, l1);
            pl[kkj][half * 2 + 1] = packbf(l2, l3);
        }

        // ---- PV phase: 4 V^T-chunks ----
#pragma unroll
        for (int ch = 0; ch < 4; ch++) {
            CP_WAIT2();
            __syncthreads();
            int pst = stage + 3; if (pst >= FL_NST) pst -= FL_NST;
            if (pf < NCH) fl_issue(sb, bh, pf, pst, tid);
            CP_COMMIT();
            pf++;
            const uint32_t stb = sb + stage * FL_STAGE;
#pragma unroll
            for (int kk = 0; kk < 2; kk++) {
                const int kkj = ch * 2 + kk;
                uint32_t vf[8][4];
#pragma unroll
                for (int dt = 0; dt < 8; dt++) LDM4(vf[dt], stb + boff[dt][kk]);
#pragma unroll
                for (int dt = 0; dt < 8; dt++) {
                    MMA16816(O[dt * 2 + 0], ph[kkj], vf[dt][0], vf[dt][1]);
                    MMA16816(O[dt * 2 + 1], ph[kkj], vf[dt][2], vf[dt][3]);
                }
#pragma unroll
                for (int dt = 0; dt < 8; dt++) {
                    MMA16816(O[dt * 2 + 0], pl[kkj], vf[dt][0], vf[dt][1]);
                    MMA16816(O[dt * 2 + 1], pl[kkj], vf[dt][2], vf[dt][3]);
                }
#pragma unroll
                for (int dt = 0; dt < 8; dt++) LDM4(vf[dt], stb + 8192 + boff[dt][kk]);
#pragma unroll
                for (int dt = 0; dt < 8; dt++) {
                    MMA16816(O[dt * 2 + 0], ph[kkj], vf[dt][0], vf[dt][1]);
                    MMA16816(O[dt * 2 + 1], ph[kkj], vf[dt][2], vf[dt][3]);
                }
            }
            if (++stage == FL_NST) stage = 0;
        }
    }

    // ---- epilogue ----
    ll0 += __shfl_xor_sync(0xffffffffu, ll0, 1);
    ll0 += __shfl_xor_sync(0xffffffffu, ll0, 2);
    ll1 += __shfl_xor_sync(0xffffffffu, ll1, 1);
    ll1 += __shfl_xor_sync(0xffffffffu, ll1, 2);
    const float inv0 = 1.f / ll0, inv1 = 1.f / ll1;
    const int t0 = m0 + w * 16 + r0, t1 = t0 + 8;
#pragma unroll
    for (int nt = 0; nt < 16; nt++) {
        int d = nt * 8 + (lane & 3) * 2;
        float v0 = O[nt][0] * inv0, v1 = O[nt][1] * inv0;
        float v2 = O[nt][2] * inv1, v3 = O[nt][3] * inv1;
        size_t b0 = ((size_t)(b * 1024 + t0)) * 2048 + h * 128 + d;
        size_t b1 = ((size_t)(b * 1024 + t1)) * 2048 + h * 128 + d;
        __nv_bfloat16 h0, h1, h2, h3, l0, l1, l2, l3;
        split2(v0, h0, l0); split2(v1, h1, l1);
        split2(v2, h2, l2); split2(v3, h3, l3);
        __nv_bfloat162 H0; H0.x = h0; H0.y = h1;
        __nv_bfloat162 L0; L0.x = l0; L0.y = l1;
        __nv_bfloat162 H1; H1.x = h2; H1.y = h3;
        __nv_bfloat162 L1; L1.x = l2; L1.y = l3;
        *(__nv_bfloat162*)(g_aoh + b0) = H0;
        *(__nv_bfloat162*)(g_aol + b0) = L0;
        *(__nv_bfloat162*)(g_aoh + b1) = H1;
        *(__nv_bfloat162*)(g_aol + b1) = L1;
    }
}

// ---------------------------------------------------------------------------
// Output projection: out = ao @ Wp^T + bp
// ---------------------------------------------------------------------------
__global__ void __launch_bounds__(256) proj_mma(const float* __restrict__ bp,
                                                float* __restrict__ out)
{
    extern __shared__ __align__(1024) char smem[];
    const int m0 = blockIdx.y * 128, n0 = blockIdx.x * 128;
    Frag F;
    mma_mainloop(smem,
        g_aoh + (size_t)m0 * CC, g_aol + (size_t)m0 * CC,
        g_wph + (size_t)n0 * CC, g_wpl + (size_t)n0 * CC, CC, CC, 64, F);

    const int lane = threadIdx.x & 31, wid = threadIdx.x >> 5;
    const int wm = wid & 3, wn = wid >> 2;
#pragma unroll
    for (int mt = 0; mt < 2; mt++)
#pragma unroll
        for (int half = 0; half < 2; half++) {
            int m = m0 + wm * 32 + mt * 16 + lane / 4 + half * 8;
#pragma unroll
            for (int nt = 0; nt < 8; nt++) {
                int n = n0 + wn * 64 + nt * 8 + (lane & 3) * 2;
                float2 bias = *(const float2*)(bp + n);
                *(float2*)(out + (size_t)m * 2048 + n) =
                    make_float2(F.c[mt][nt][half * 2] + bias.x,
                                F.c[mt][nt][half * 2 + 1] + bias.y);
            }
        }
}

// ---------------------------------------------------------------------------
extern "C" void kernel_launch(void* const* d_in, const int* in_sizes, int n_in,
                              void* d_out, int out_size)
{
    (void)in_sizes; (void)n_in; (void)out_size;
    const float* x      = (const float*)d_in[0];
    const float* past_k = (const float*)d_in[1];
    const float* past_v = (const float*)d_in[2];
    const float* Wk     = (const float*)d_in[3];
    const float* Wq     = (const float*)d_in[4];
    const float* Wv     = (const float*)d_in[5];
    const float* Wp     = (const float*)d_in[6];
    const float* bp     = (const float*)d_in[7];

    float* out  = (float*)d_out;
    float* outk = out + (size_t)BB * TT * CC;
    float* outv = outk + (size_t)BHN * TOTL * DD;

    cudaFuncSetAttribute(qkv_mma,   cudaFuncAttributeMaxDynamicSharedMemorySize, DSMEM);
    cudaFuncSetAttribute(proj_mma,  cudaFuncAttributeMaxDynamicSharedMemorySize, DSMEM);
    cudaFuncSetAttribute(flash_mma, cudaFuncAttributeMaxDynamicSharedMemorySize, FL_DSMEM);

    // 1-2. fused prep: splits + past-KV copy
    prep_kernel<<<dim3(4096, 7), 256>>>(
        (const float4*)x,  (const float4*)Wq, (const float4*)Wk,
        (const float4*)Wv, (const float4*)Wp, (const float4*)past_k,
        (const float4*)past_v, (float4*)outk, (float4*)outv);

    // 3. QKV projection
    qkv_mma<<<dim3(16, 16, 3), 256, DSMEM>>>(outk, outv);

    // 4. transpose+split V cache
    vtrans_kernel<<<dim3(64, 4, 32), 256>>>(outv);

    // 5-7. fused flash attention
    flash_mma<<<dim3(1, 8, 32), 256, FL_DSMEM>>>();

    // 8. output projection + bias
    proj_mma<<<dim3(16, 16), 256, DSMEM>>>(bp, out);
}

// round 9
// speedup vs baseline: 5.1415x; 1.1033x over previous
#include <cuda_runtime.h>
#include <cuda_bf16.h>
#include <math.h>
#include <stdint.h>

// Problem constants
#define BB   2
#define TT   1024
#define CC   2048
#define HH   16
#define DD   128
#define PP   1024
#define TOTL 2048
#define BHN  32

#define STAGE_BYTES 32768
#define NSTAGE      3
#define DSMEM       (NSTAGE * STAGE_BYTES)   // 96 KB (2 CTA/SM)

// flash kernel smem: 4-stage K/V ring (64KB) + Q 64x128 hi/lo (32KB)
#define FL_STAGE  16384
#define FL_NST    4
#define FL_QOFF   (FL_NST * FL_STAGE)        // 65536
#define FL_DSMEM  (FL_QOFF + 32768)          // 98304 (2 CTA/SM)

// ---------------------------------------------------------------------------
// Device scratch (allocation-free)
// ---------------------------------------------------------------------------
__device__ __nv_bfloat16 g_xh [(size_t)CC * CC], g_xl [(size_t)CC * CC];
__device__ __nv_bfloat16 g_wqh[(size_t)CC * CC], g_wql[(size_t)CC * CC];
__device__ __nv_bfloat16 g_wkh[(size_t)CC * CC], g_wkl[(size_t)CC * CC];
__device__ __nv_bfloat16 g_wvh[(size_t)CC * CC], g_wvl[(size_t)CC * CC];
__device__ __nv_bfloat16 g_wph[(size_t)CC * CC], g_wpl[(size_t)CC * CC];
__device__ __nv_bfloat16 g_qh [(size_t)BHN * TT * DD],   g_ql [(size_t)BHN * TT * DD];
__device__ __nv_bfloat16 g_kh [(size_t)BHN * TOTL * DD], g_kl [(size_t)BHN * TOTL * DD];
__device__ __nv_bfloat16 g_vth[(size_t)BHN * DD * TOTL], g_vtl[(size_t)BHN * DD * TOTL];
__device__ __nv_bfloat16 g_aoh[(size_t)BB * TT * CC],    g_aol[(size_t)BB * TT * CC];

__device__ __forceinline__ uint32_t smem_u32(const void* p) {
    uint32_t a;
    asm("{ .reg .u64 t; cvta.to.shared.u64 t, %1; cvt.u32.u64 %0, t; }" : "=r"(a) : "l"(p));
    return a;
}
__device__ __forceinline__ void split2(float v, __nv_bfloat16& h, __nv_bfloat16& l) {
    h = __float2bfloat16(v);
    l = __float2bfloat16(v - __bfloat162float(h));
}
__device__ __forceinline__ uint32_t packbf(__nv_bfloat16 a, __nv_bfloat16 b) {
    __nv_bfloat162 t; t.x = a; t.y = b;
    return *(uint32_t*)&t;
}
__device__ __forceinline__ void cpasync16(uint32_t dst, const void* src) {
    asm volatile("cp.async.cg.shared.global [%0], [%1], 16;" :: "r"(dst), "l"(src));
}
#define CP_COMMIT() asm volatile("cp.async.commit_group;" ::: "memory")
#define CP_WAIT1()  asm volatile("cp.async.wait_group 1;"  ::: "memory")
#define CP_WAIT2()  asm volatile("cp.async.wait_group 2;"  ::: "memory")

#define LDM4(r, addr)                                                        \
    asm volatile("ldmatrix.sync.aligned.m8n8.x4.shared.b16 {%0,%1,%2,%3}, [%4];" \
        : "=r"((r)[0]), "=r"((r)[1]), "=r"((r)[2]), "=r"((r)[3]) : "r"(addr))

#define MMA16816(c, a, b0v, b1v)                                             \
    asm volatile("mma.sync.aligned.m16n8k16.row.col.f32.bf16.bf16.f32 "      \
        "{%0,%1,%2,%3}, {%4,%5,%6,%7}, {%8,%9}, {%0,%1,%2,%3};"              \
        : "+f"((c)[0]), "+f"((c)[1]), "+f"((c)[2]), "+f"((c)[3])             \
        : "r"((a)[0]), "r"((a)[1]), "r"((a)[2]), "r"((a)[3]),                \
          "r"(b0v), "r"(b1v))

__device__ __forceinline__ uint32_t swz(uint32_t o) { return o ^ ((o >> 3) & 0x30); }

// ---------------------------------------------------------------------------
// Dense GEMM mainloop: 3-stage cp.async ring, 8 warps 4x2, CTA 128x128,
// K-chunk 32, C = AhBh + AlBh + AhBl (term groups separated).
// ---------------------------------------------------------------------------
struct Frag { float c[2][8][4]; };

__device__ __forceinline__ void mma_mainloop(
    char* smem,
    const __nv_bfloat16* __restrict__ Ah, const __nv_bfloat16* __restrict__ Al,
    const __nv_bfloat16* __restrict__ Bh, const __nv_bfloat16* __restrict__ Bl,
    size_t ldA, size_t ldB, int NC, Frag& F)
{
    const uint32_t sb = smem_u32(smem);
    const int tid  = threadIdx.x;
    const int lane = tid & 31;
    const int wid  = tid >> 5;
    const int wm   = wid & 3;
    const int wn   = wid >> 2;

#pragma unroll
    for (int i = 0; i < 2; i++)
#pragma unroll
        for (int j = 0; j < 8; j++)
#pragma unroll
            for (int k = 0; k < 4; k++) F.c[i][j][k] = 0.f;

    const __nv_bfloat16* gp[8];
    uint32_t soff[8];
#pragma unroll
    for (int j = 0; j < 8; j++) {
        int u = tid + 256 * (j & 1);
        int row = u >> 2, un = u & 3, T = j >> 1;
        const __nv_bfloat16* base = (T == 0) ? Ah : (T == 1) ? Al : (T == 2) ? Bh : Bl;
        size_t ld = (T < 2) ? ldA : ldB;
        gp[j]   = base + (size_t)row * ld + un * 8;
        soff[j] = T * 8192 + swz(row * 64 + un * 16);
    }

    uint32_t aoff[2][2], boff[4][2];
#pragma unroll
    for (int mt = 0; mt < 2; mt++)
#pragma unroll
        for (int kk = 0; kk < 2; kk++) {
            int row = wm * 32 + mt * 16 + (lane & 15);
            aoff[mt][kk] = swz(row * 64 + kk * 32 + ((lane >> 4) & 1) * 16);
        }
#pragma unroll
    for (int bt = 0; bt < 4; bt++)
#pragma unroll
        for (int kk = 0; kk < 2; kk++) {
            int row = wn * 64 + bt * 16 + (lane & 7) + ((lane >> 4) & 1) * 8;
            boff[bt][kk] = swz(row * 64 + kk * 32 + ((lane >> 3) & 1) * 16);
        }

#pragma unroll
    for (int p = 0; p < 2; p++) {
        if (p < NC) {
            uint32_t st = sb + p * STAGE_BYTES;
#pragma unroll
            for (int j = 0; j < 8; j++)
                cpasync16(st + soff[j], gp[j] + (size_t)p * 32);
        }
        CP_COMMIT();
    }

    int stage = 0;
    for (int ch = 0; ch < NC; ch++) {
        CP_WAIT1();
        __syncthreads();

        const int pf = ch + 2;
        if (pf < NC) {
            int pstage = stage + 2; if (pstage >= NSTAGE) pstage -= NSTAGE;
            uint32_t st = sb + pstage * STAGE_BYTES;
#pragma unroll
            for (int j = 0; j < 8; j++)
                cpasync16(st + soff[j], gp[j] + (size_t)pf * 32);
        }
        CP_COMMIT();

        const uint32_t stb = sb + stage * STAGE_BYTES;
#pragma unroll
        for (int kk = 0; kk < 2; kk++) {
            uint32_t ah[2][4], al[2][4], bf4[4][4];
#pragma unroll
            for (int mt = 0; mt < 2; mt++) LDM4(ah[mt], stb + aoff[mt][kk]);
#pragma unroll
            for (int mt = 0; mt < 2; mt++) LDM4(al[mt], stb + 8192 + aoff[mt][kk]);
#pragma unroll
            for (int bt = 0; bt < 4; bt++) LDM4(bf4[bt], stb + 16384 + boff[bt][kk]);
#pragma unroll
            for (int mt = 0; mt < 2; mt++)
#pragma unroll
                for (int bt = 0; bt < 4; bt++) {
                    MMA16816(F.c[mt][bt * 2 + 0], ah[mt], bf4[bt][0], bf4[bt][1]);
                    MMA16816(F.c[mt][bt * 2 + 1], ah[mt], bf4[bt][2], bf4[bt][3]);
                }
#pragma unroll
            for (int mt = 0; mt < 2; mt++)
#pragma unroll
                for (int bt = 0; bt < 4; bt++) {
                    MMA16816(F.c[mt][bt * 2 + 0], al[mt], bf4[bt][0], bf4[bt][1]);
                    MMA16816(F.c[mt][bt * 2 + 1], al[mt], bf4[bt][2], bf4[bt][3]);
                }
#pragma unroll
            for (int bt = 0; bt < 4; bt++) LDM4(bf4[bt], stb + 24576 + boff[bt][kk]);
#pragma unroll
            for (int mt = 0; mt < 2; mt++)
#pragma unroll
                for (int bt = 0; bt < 4; bt++) {
                    MMA16816(F.c[mt][bt * 2 + 0], ah[mt], bf4[bt][0], bf4[bt][1]);
                    MMA16816(F.c[mt][bt * 2 + 1], ah[mt], bf4[bt][2], bf4[bt][3]);
                }
        }
        if (++stage == NSTAGE) stage = 0;
    }
}

// ---------------------------------------------------------------------------
// Fused prep: tasks 0-4 split {x,Wq,Wk,Wv,Wp}; 5 = past_k copy+split; 6 = past_v copy
// ---------------------------------------------------------------------------
__global__ void __launch_bounds__(256) prep_kernel(
    const float4* __restrict__ x,  const float4* __restrict__ Wq,
    const float4* __restrict__ Wk, const float4* __restrict__ Wv,
    const float4* __restrict__ Wp, const float4* __restrict__ pk,
    const float4* __restrict__ pv, float4* __restrict__ outk,
    float4* __restrict__ outv)
{
    const int task = blockIdx.y;
    const int i = blockIdx.x * blockDim.x + threadIdx.x;

    if (task == 6) {
        int bh = i >> 15, rem = i & 32767;
        outv[(size_t)bh * (TOTL * DD / 4) + rem] = pv[i];
        return;
    }

    float4 v;
    __nv_bfloat162 *dh, *dl;
    size_t o2;
    if (task == 5) {
        int bh = i >> 15, rem = i & 32767;
        size_t d4 = (size_t)bh * (TOTL * DD / 4) + rem;
        v = pk[i];
        outk[d4] = v;
        dh = (__nv_bfloat162*)g_kh; dl = (__nv_bfloat162*)g_kl;
        o2 = 2 * d4;
    } else {
        const float4* s = (task == 0) ? x : (task == 1) ? Wq :
                          (task == 2) ? Wk : (task == 3) ? Wv : Wp;
        v = s[i];
        dh = (__nv_bfloat162*)((task == 0) ? g_xh : (task == 1) ? g_wqh :
                               (task == 2) ? g_wkh : (task == 3) ? g_wvh : g_wph);
        dl = (__nv_bfloat162*)((task == 0) ? g_xl : (task == 1) ? g_wql :
                               (task == 2) ? g_wkl : (task == 3) ? g_wvl : g_wpl);
        o2 = 2 * (size_t)i;
    }
    __nv_bfloat16 h0, h1, h2, h3, l0, l1, l2, l3;
    split2(v.x, h0, l0); split2(v.y, h1, l1);
    split2(v.z, h2, l2); split2(v.w, h3, l3);
    __nv_bfloat162 H0; H0.x = h0; H0.y = h1;
    __nv_bfloat162 H1; H1.x = h2; H1.y = h3;
    __nv_bfloat162 L0; L0.x = l0; L0.y = l1;
    __nv_bfloat162 L1; L1.x = l2; L1.y = l3;
    dh[o2] = H0; dh[o2 + 1] = H1;
    dl[o2] = L0; dl[o2 + 1] = L1;
}

// v[bh][j][d] fp32 -> vt hi/lo [bh][d][j] bf16
__global__ void __launch_bounds__(256) vtrans_kernel(const float* __restrict__ v)
{
    __shared__ float tile[32][33];
    const int bh = blockIdx.z;
    const int j0 = blockIdx.x * 32, d0 = blockIdx.y * 32;
    const int tx = threadIdx.x & 31, ty = threadIdx.x >> 5;
    const float* src = v + (size_t)bh * TOTL * DD;
#pragma unroll
    for (int i = 0; i < 4; i++)
        tile[ty + i * 8][tx] = src[(size_t)(j0 + ty + i * 8) * DD + d0 + tx];
    __syncthreads();
    __nv_bfloat16* dh = g_vth + (size_t)bh * DD * TOTL;
    __nv_bfloat16* dl = g_vtl + (size_t)bh * DD * TOTL;
#pragma unroll
    for (int i = 0; i < 4; i++) {
        int d = d0 + ty + i * 8, j = j0 + tx;
        float val = tile[tx][ty + i * 8];
        __nv_bfloat16 h, l; split2(val, h, l);
        dh[(size_t)d * TOTL + j] = h;
        dl[(size_t)d * TOTL + j] = l;
    }
}

// ---------------------------------------------------------------------------
// QKV projection: y = x @ W^T, z selects {Wq, Wk, Wv}
// ---------------------------------------------------------------------------
__global__ void __launch_bounds__(256, 2) qkv_mma(float* __restrict__ outk,
                                                  float* __restrict__ outv)
{
    extern __shared__ __align__(1024) char smem[];
    const int z = blockIdx.z;
    const int m0 = blockIdx.y * 128, n0 = blockIdx.x * 128;
    const __nv_bfloat16* Bh = (z == 0) ? g_wqh : (z == 1) ? g_wkh : g_wvh;
    const __nv_bfloat16* Bl = (z == 0) ? g_wql : (z == 1) ? g_wkl : g_wvl;
    Frag F;
    mma_mainloop(smem,
        g_xh + (size_t)m0 * CC, g_xl + (size_t)m0 * CC,
        Bh + (size_t)n0 * CC,   Bl + (size_t)n0 * CC, CC, CC, 64, F);

    const int lane = threadIdx.x & 31, wid = threadIdx.x >> 5;
    const int wm = wid & 3, wn = wid >> 2;
#pragma unroll
    for (int mt = 0; mt < 2; mt++)
#pragma unroll
        for (int half = 0; half < 2; half++) {
            int m = m0 + wm * 32 + mt * 16 + lane / 4 + half * 8;
            int b = m >> 10, t = m & 1023;
#pragma unroll
            for (int nt = 0; nt < 8; nt++) {
                int n = n0 + wn * 64 + nt * 8 + (lane & 3) * 2;
                int h = n >> 7, d = n & 127;
                float v0 = F.c[mt][nt][half * 2], v1 = F.c[mt][nt][half * 2 + 1];
                if (z == 0) {
                    size_t base = (((size_t)(b * 16 + h)) * 1024 + t) * 128 + d;
                    __nv_bfloat16 h0, h1, l0, l1;
                    split2(v0, h0, l0); split2(v1, h1, l1);
                    *(__nv_bfloat162*)(g_qh + base) = *(__nv_bfloat162*)&(uint32_t&)
                        (*(uint32_t[]){packbf(h0, h1)});
                    *(__nv_bfloat162*)(g_ql + base) = *(__nv_bfloat162*)&(uint32_t&)
                        (*(uint32_t[]){packbf(l0, l1)});
                } else if (z == 1) {
                    size_t base = (((size_t)(b * 16 + h)) * 2048 + 1024 + t) * 128 + d;
                    *(float2*)(outk + base) = make_float2(v0, v1);
                    __nv_bfloat16 h0, h1, l0, l1;
                    split2(v0, h0, l0); split2(v1, h1, l1);
                    uint32_t ph = packbf(h0, h1), plv = packbf(l0, l1);
                    *(uint32_t*)(g_kh + base) = ph;
                    *(uint32_t*)(g_kl + base) = plv;
                } else {
                    size_t base = (((size_t)(b * 16 + h)) * 2048 + 1024 + t) * 128 + d;
                    *(float2*)(outv + base) = make_float2(v0, v1);
                }
            }
        }
}

// ---------------------------------------------------------------------------
// Flash attention: 64 q-rows per CTA, 128 threads (4 warps x m16 x n128),
// 2 CTAs/SM so softmax overlaps MMA across CTAs.
// ---------------------------------------------------------------------------
__device__ __forceinline__ void fl_issue(uint32_t sb, int bh, int idx, int stg, int tid)
{
    const int jt = idx >> 3, ch = idx & 3;
    const int isV = (idx >> 2) & 1;
    const __nv_bfloat16 *sh, *sl;
    size_t ld;
    if (!isV) {
        sh = g_kh + ((size_t)bh * TOTL + jt * 128) * DD + ch * 32;
        sl = g_kl + ((size_t)bh * TOTL + jt * 128) * DD + ch * 32;
        ld = DD;
    } else {
        sh = g_vth + (size_t)bh * DD * TOTL + jt * 128 + ch * 32;
        sl = g_vtl + (size_t)bh * DD * TOTL + jt * 128 + ch * 32;
        ld = TOTL;
    }
    uint32_t st = sb + stg * FL_STAGE;
#pragma unroll
    for (int j = 0; j < 4; j++) {
        int u = tid + 128 * j, row = u >> 2, un = u & 3;
        uint32_t so = swz(row * 64 + un * 16);
        cpasync16(st + so,        sh + (size_t)row * ld + un * 8);
        cpasync16(st + 8192 + so, sl + (size_t)row * ld + un * 8);
    }
}

__global__ void __launch_bounds__(128) flash_mma()
{
    extern __shared__ __align__(1024) char smem[];
    const uint32_t sb = smem_u32(smem);
    const int bh = blockIdx.z;
    const int m0 = blockIdx.y * 64;
    const int b = bh >> 4, h = bh & 15;
    const int tid = threadIdx.x;
    const int lane = tid & 31;
    const int w = tid >> 5;
    const int r0 = lane >> 2;
    const int NJ = (1215 + m0) >> 7;                 // ceil((1088+m0)/128)
    const int NCH = NJ * 8;
    const int off = 1024 + m0 - (NJ - 1) * 128;      // diag offset in last tile

    // Q tile: 64 rows, 4 k-chunks x (hi,lo), 4KB per chunk per part
#pragma unroll
    for (int c = 0; c < 4; c++)
#pragma unroll
        for (int j = 0; j < 2; j++) {
            int u = tid + 128 * j, row = u >> 2, un = u & 3;
            uint32_t so = c * 4096 + swz(row * 64 + un * 16);
            cpasync16(sb + FL_QOFF + so,
                      g_qh + ((size_t)bh * TT + m0 + row) * DD + c * 32 + un * 8);
            cpasync16(sb + FL_QOFF + 16384 + so,
                      g_ql + ((size_t)bh * TT + m0 + row) * DD + c * 32 + un * 8);
        }
    CP_COMMIT();
    fl_issue(sb, bh, 0, 0, tid); CP_COMMIT();
    fl_issue(sb, bh, 1, 1, tid); CP_COMMIT();
    fl_issue(sb, bh, 2, 2, tid); CP_COMMIT();

    uint32_t aoff[2], boff[8][2];
#pragma unroll
    for (int kk = 0; kk < 2; kk++) {
        int row = w * 16 + (lane & 15);
        aoff[kk] = swz(row * 64 + kk * 32 + ((lane >> 4) & 1) * 16);
    }
#pragma unroll
    for (int bt = 0; bt < 8; bt++)
#pragma unroll
        for (int kk = 0; kk < 2; kk++) {
            int row = bt * 16 + (lane & 7) + ((lane >> 4) & 1) * 8;
            boff[bt][kk] = swz(row * 64 + kk * 32 + ((lane >> 3) & 1) * 16);
        }

    float O[16][4];
#pragma unroll
    for (int i = 0; i < 16; i++)
#pragma unroll
        for (int k = 0; k < 4; k++) O[i][k] = 0.f;
    float ml0 = -1e30f, ml1 = -1e30f;
    float ll0 = 0.f, ll1 = 0.f;
    uint32_t ph[8][4], pl[8][4];

    int pf = 3, stage = 0;
    const float scale = 0.08838834764831845f;

    for (int jt = 0; jt < NJ; jt++) {
        float Sf[16][4];
        // ---- S phase: 4 K-chunks ----
#pragma unroll
        for (int ch = 0; ch < 4; ch++) {
            CP_WAIT2();
            __syncthreads();
            int pst = stage + 3; if (pst >= FL_NST) pst -= FL_NST;
            if (pf < NCH) fl_issue(sb, bh, pf, pst, tid);
            CP_COMMIT();
            pf++;
            const uint32_t stb = sb + stage * FL_STAGE;
            const uint32_t qb  = sb + FL_QOFF + ch * 4096;
            if (ch == 0) {
#pragma unroll
                for (int i = 0; i < 16; i++)
#pragma unroll
                    for (int k = 0; k < 4; k++) Sf[i][k] = 0.f;
            }
#pragma unroll
            for (int kk = 0; kk < 2; kk++) {
                uint32_t ahf[4], alf[4], bf[8][4];
                LDM4(ahf, qb + aoff[kk]);
                LDM4(alf, qb + 16384 + aoff[kk]);
#pragma unroll
                for (int bt = 0; bt < 8; bt++) LDM4(bf[bt], stb + boff[bt][kk]);
#pragma unroll
                for (int bt = 0; bt < 8; bt++) {
                    MMA16816(Sf[bt * 2 + 0], ahf, bf[bt][0], bf[bt][1]);
                    MMA16816(Sf[bt * 2 + 1], ahf, bf[bt][2], bf[bt][3]);
                }
#pragma unroll
                for (int bt = 0; bt < 8; bt++) {
                    MMA16816(Sf[bt * 2 + 0], alf, bf[bt][0], bf[bt][1]);
                    MMA16816(Sf[bt * 2 + 1], alf, bf[bt][2], bf[bt][3]);
                }
#pragma unroll
                for (int bt = 0; bt < 8; bt++) LDM4(bf[bt], stb + 8192 + boff[bt][kk]);
#pragma unroll
                for (int bt = 0; bt < 8; bt++) {
                    MMA16816(Sf[bt * 2 + 0], ahf, bf[bt][0], bf[bt][1]);
                    MMA16816(Sf[bt * 2 + 1], ahf, bf[bt][2], bf[bt][3]);
                }
            }
            if (++stage == FL_NST) stage = 0;
        }

        // ---- online softmax ----
#pragma unroll
        for (int nt = 0; nt < 16; nt++)
#pragma unroll
            for (int ci = 0; ci < 4; ci++) Sf[nt][ci] *= scale;
        if (jt == NJ - 1) {
#pragma unroll
            for (int nt = 0; nt < 16; nt++)
#pragma unroll
                for (int ci = 0; ci < 4; ci++) {
                    int jj = nt * 8 + (lane & 3) * 2 + (ci & 1);
                    int tl = w * 16 + r0 + ((ci >> 1) << 3);
                    if (jj > off + tl) Sf[nt][ci] = -1e30f;
                }
        }
        float mc0 = -1e30f, mc1 = -1e30f;
#pragma unroll
        for (int nt = 0; nt < 16; nt++) {
            mc0 = fmaxf(mc0, fmaxf(Sf[nt][0], Sf[nt][1]));
            mc1 = fmaxf(mc1, fmaxf(Sf[nt][2], Sf[nt][3]));
        }
        mc0 = fmaxf(mc0, __shfl_xor_sync(0xffffffffu, mc0, 1));
        mc0 = fmaxf(mc0, __shfl_xor_sync(0xffffffffu, mc0, 2));
        mc1 = fmaxf(mc1, __shfl_xor_sync(0xffffffffu, mc1, 1));
        mc1 = fmaxf(mc1, __shfl_xor_sync(0xffffffffu, mc1, 2));
        float mn0 = fmaxf(ml0, mc0), mn1 = fmaxf(ml1, mc1);
        float a0 = __expf(ml0 - mn0), a1 = __expf(ml1 - mn1);
        ml0 = mn0; ml1 = mn1;
        ll0 *= a0; ll1 *= a1;
#pragma unroll
        for (int nt = 0; nt < 16; nt++) {
            O[nt][0] *= a0; O[nt][1] *= a0;
            O[nt][2] *= a1; O[nt][3] *= a1;
        }
#pragma unroll
        for (int nt = 0; nt < 16; nt++) {
            float p0 = __expf(Sf[nt][0] - mn0), p1 = __expf(Sf[nt][1] - mn0);
            float p2 = __expf(Sf[nt][2] - mn1), p3 = __expf(Sf[nt][3] - mn1);
            ll0 += p0 + p1; ll1 += p2 + p3;
            __nv_bfloat16 h0, h1, h2, h3, l0, l1, l2, l3;
            split2(p0, h0, l0); split2(p1, h1, l1);
            split2(p2, h2, l2); split2(p3, h3, l3);
            int kkj = nt >> 1, half = nt & 1;
            ph[kkj][half * 2 + 0] = packbf(h0, h1);
            ph[kkj][half * 2 + 1] = packbf(h2, h3);
            pl[kkj][half * 2 + 0] = packbf(l0, l1);
            pl[kkj][half * 2 + 1] = packbf(l2, l3);
        }

        // ---- PV phase: 4 V^T-chunks ----
#pragma unroll
        for (int ch = 0; ch < 4; ch++) {
            CP_WAIT2();
            __syncthreads();
            int pst = stage + 3; if (pst >= FL_NST) pst -= FL_NST;
            if (pf < NCH) fl_issue(sb, bh, pf, pst, tid);
            CP_COMMIT();
            pf++;
            const uint32_t stb = sb + stage * FL_STAGE;
#pragma unroll
            for (int kk = 0; kk < 2; kk++) {
                const int kkj = ch * 2 + kk;
                uint32_t vf[8][4];
#pragma unroll
                for (int dt = 0; dt < 8; dt++) LDM4(vf[dt], stb + boff[dt][kk]);
#pragma unroll
                for (int dt = 0; dt < 8; dt++) {
                    MMA16816(O[dt * 2 + 0], ph[kkj], vf[dt][0], vf[dt][1]);
                    MMA16816(O[dt * 2 + 1], ph[kkj], vf[dt][2], vf[dt][3]);
                }
#pragma unroll
                for (int dt = 0; dt < 8; dt++) {
                    MMA16816(O[dt * 2 + 0], pl[kkj], vf[dt][0], vf[dt][1]);
                    MMA16816(O[dt * 2 + 1], pl[kkj], vf[dt][2], vf[dt][3]);
                }
#pragma unroll
                for (int dt = 0; dt < 8; dt++) LDM4(vf[dt], stb + 8192 + boff[dt][kk]);
#pragma unroll
                for (int dt = 0; dt < 8; dt++) {
                    MMA16816(O[dt * 2 + 0], ph[kkj], vf[dt][0], vf[dt][1]);
                    MMA16816(O[dt * 2 + 1], ph[kkj], vf[dt][2], vf[dt][3]);
                }
            }
            if (++stage == FL_NST) stage = 0;
        }
    }

    // ---- epilogue ----
    ll0 += __shfl_xor_sync(0xffffffffu, ll0, 1);
    ll0 += __shfl_xor_sync(0xffffffffu, ll0, 2);
    ll1 += __shfl_xor_sync(0xffffffffu, ll1, 1);
    ll1 += __shfl_xor_sync(0xffffffffu, ll1, 2);
    const float inv0 = 1.f / ll0, inv1 = 1.f / ll1;
    const int t0 = m0 + w * 16 + r0, t1 = t0 + 8;
#pragma unroll
    for (int nt = 0; nt < 16; nt++) {
        int d = nt * 8 + (lane & 3) * 2;
        float v0 = O[nt][0] * inv0, v1 = O[nt][1] * inv0;
        float v2 = O[nt][2] * inv1, v3 = O[nt][3] * inv1;
        size_t b0 = ((size_t)(b * 1024 + t0)) * 2048 + h * 128 + d;
        size_t b1 = ((size_t)(b * 1024 + t1)) * 2048 + h * 128 + d;
        __nv_bfloat16 h0, h1, h2, h3, l0, l1, l2, l3;
        split2(v0, h0, l0); split2(v1, h1, l1);
        split2(v2, h2, l2); split2(v3, h3, l3);
        *(uint32_t*)(g_aoh + b0) = packbf(h0, h1);
        *(uint32_t*)(g_aol + b0) = packbf(l0, l1);
        *(uint32_t*)(g_aoh + b1) = packbf(h2, h3);
        *(uint32_t*)(g_aol + b1) = packbf(l2, l3);
    }
}

// ---------------------------------------------------------------------------
// Output projection: out = ao @ Wp^T + bp
// ---------------------------------------------------------------------------
__global__ void __launch_bounds__(256, 2) proj_mma(const float* __restrict__ bp,
                                                    float* __restrict__ out)
{
    extern __shared__ __align__(1024) char smem[];
    const int m0 = blockIdx.y * 128, n0 = blockIdx.x * 128;
    Frag F;
    mma_mainloop(smem,
        g_aoh + (size_t)m0 * CC, g_aol + (size_t)m0 * CC,
        g_wph + (size_t)n0 * CC, g_wpl + (size_t)n0 * CC, CC, CC, 64, F);

    const int lane = threadIdx.x & 31, wid = threadIdx.x >> 5;
    const int wm = wid & 3, wn = wid >> 2;
#pragma unroll
    for (int mt = 0; mt < 2; mt++)
#pragma unroll
        for (int half = 0; half < 2; half++) {
            int m = m0 + wm * 32 + mt * 16 + lane / 4 + half * 8;
#pragma unroll
            for (int nt = 0; nt < 8; nt++) {
                int n = n0 + wn * 64 + nt * 8 + (lane & 3) * 2;
                float2 bias = *(const float2*)(bp + n);
                *(float2*)(out + (size_t)m * 2048 + n) =
                    make_float2(F.c[mt][nt][half * 2] + bias.x,
                                F.c[mt][nt][half * 2 + 1] + bias.y);
            }
        }
}

// ---------------------------------------------------------------------------
extern "C" void kernel_launch(void* const* d_in, const int* in_sizes, int n_in,
                              void* d_out, int out_size)
{
    (void)in_sizes; (void)n_in; (void)out_size;
    const float* x      = (const float*)d_in[0];
    const float* past_k = (const float*)d_in[1];
    const float* past_v = (const float*)d_in[2];
    const float* Wk     = (const float*)d_in[3];
    const float* Wq     = (const float*)d_in[4];
    const float* Wv     = (const float*)d_in[5];
    const float* Wp     = (const float*)d_in[6];
    const float* bp     = (const float*)d_in[7];

    float* out  = (float*)d_out;
    float* outk = out + (size_t)BB * TT * CC;
    float* outv = outk + (size_t)BHN * TOTL * DD;

    cudaFuncSetAttribute(qkv_mma,   cudaFuncAttributeMaxDynamicSharedMemorySize, DSMEM);
    cudaFuncSetAttribute(proj_mma,  cudaFuncAttributeMaxDynamicSharedMemorySize, DSMEM);
    cudaFuncSetAttribute(flash_mma, cudaFuncAttributeMaxDynamicSharedMemorySize, FL_DSMEM);

    // 1-2. fused prep
    prep_kernel<<<dim3(4096, 7), 256>>>(
        (const float4*)x,  (const float4*)Wq, (const float4*)Wk,
        (const float4*)Wv, (const float4*)Wp, (const float4*)past_k,
        (const float4*)past_v, (float4*)outk, (float4*)outv);

    // 3. QKV projection
    qkv_mma<<<dim3(16, 16, 3), 256, DSMEM>>>(outk, outv);

    // 4. transpose+split V cache
    vtrans_kernel<<<dim3(64, 4, 32), 256>>>(outv);

    // 5-7. fused flash attention (64 q-rows per CTA, 2 CTAs/SM)
    flash_mma<<<dim3(1, 16, 32), 128, FL_DSMEM>>>();

    // 8. output projection + bias
    proj_mma<<<dim3(16, 16), 256, DSMEM>>>(bp, out);
}